// round 2
// baseline (speedup 1.0000x reference)
#include <cuda_runtime.h>

#define N_NODES 20000
#define MAXC 256
#define MAXE 360000

// ---------------- scratch (device globals: no allocation allowed) ----------------
__device__ float g_deg[N_NODES];
__device__ float g_dis[N_NODES];
__device__ int   g_src[MAXE];
__device__ int   g_dst[MAXE];
__device__ float g_enorm[MAXE];
__device__ float g_h[(size_t)N_NODES * MAXC];    // GEMM output (pre-aggregation)
__device__ float g_agg[(size_t)N_NODES * MAXC];  // scatter accumulator
__device__ float g_t[(size_t)N_NODES * MAXC];    // layer activation

// ---------------- degree / norm ----------------
__global__ void deg_init_kernel() {
    int i = blockIdx.x * blockDim.x + threadIdx.x;
    if (i < N_NODES) g_deg[i] = 1.0f;  // self-loop contributes 1
}

// edge_index is int32 (JAX without x64 downcasts int64 -> int32)
__global__ void deg_count_kernel(const int* __restrict__ ei, int E) {
    int e = blockIdx.x * blockDim.x + threadIdx.x;
    if (e < E) atomicAdd(&g_deg[ei[E + e]], 1.0f);
}

__global__ void dis_kernel() {
    int i = blockIdx.x * blockDim.x + threadIdx.x;
    if (i < N_NODES) g_dis[i] = rsqrtf(g_deg[i]);
}

__global__ void prep_edges_kernel(const int* __restrict__ ei, int E) {
    int e = blockIdx.x * blockDim.x + threadIdx.x;
    if (e < E) {
        int s = ei[e];
        int d = ei[E + e];
        g_src[e] = s;
        g_dst[e] = d;
        g_enorm[e] = g_dis[s] * g_dis[d];
    }
}

// ---------------- GEMM: C[M,N] = A[M,K] @ B[K,N], fp32, register-tiled ----------------
// BM=BN=64, BK=16, 256 threads, 4x4 micro-tile per thread.
// Requires: K % 16 == 0, N % 64 == 0 (true for all 3 layers). M guarded.
__global__ void gemm_kernel(const float* __restrict__ A, const float* __restrict__ B,
                            float* __restrict__ C, int M, int N, int K) {
    const int BM = 64, BN = 64, BK = 16;
    __shared__ float As[BK][BM];
    __shared__ float Bs[BK][BN];

    int tid = threadIdx.x;
    int brow = blockIdx.y * BM;
    int bcol = blockIdx.x * BN;
    int ty = tid >> 4;   // 0..15
    int tx = tid & 15;   // 0..15

    float acc[4][4] = {};

    for (int k0 = 0; k0 < K; k0 += BK) {
        // load A tile (64 rows x 16 cols), As stored [k][m]
        #pragma unroll
        for (int i = 0; i < 4; i++) {
            int lin = tid + i * 256;
            int m = lin >> 4;
            int k = lin & 15;
            int gr = brow + m;
            float v = 0.0f;
            if (gr < M) v = A[(size_t)gr * K + k0 + k];
            As[k][m] = v;
        }
        // load B tile (16 rows x 64 cols)
        #pragma unroll
        for (int i = 0; i < 4; i++) {
            int lin = tid + i * 256;
            int k = lin >> 6;
            int n = lin & 63;
            Bs[k][n] = B[(size_t)(k0 + k) * N + bcol + n];
        }
        __syncthreads();

        #pragma unroll
        for (int k = 0; k < BK; k++) {
            float4 a4 = *(const float4*)&As[k][ty * 4];
            float4 b4 = *(const float4*)&Bs[k][tx * 4];
            float ar[4] = {a4.x, a4.y, a4.z, a4.w};
            float br[4] = {b4.x, b4.y, b4.z, b4.w};
            #pragma unroll
            for (int i = 0; i < 4; i++)
                #pragma unroll
                for (int j = 0; j < 4; j++)
                    acc[i][j] = fmaf(ar[i], br[j], acc[i][j]);
        }
        __syncthreads();
    }

    #pragma unroll
    for (int i = 0; i < 4; i++) {
        int gr = brow + ty * 4 + i;
        if (gr < M) {
            float4 v = make_float4(acc[i][0], acc[i][1], acc[i][2], acc[i][3]);
            *(float4*)&C[(size_t)gr * N + bcol + tx * 4] = v;
        }
    }
}

// ---------------- zero ----------------
__global__ void zero_kernel(float* __restrict__ p, int n4) {
    int i = blockIdx.x * blockDim.x + threadIdx.x;
    if (i < n4) ((float4*)p)[i] = make_float4(0.f, 0.f, 0.f, 0.f);
}

// ---------------- scatter: agg[dst] += h[src] * norm ----------------
// one thread per (edge, 4 columns); vshift = log2(C/4)
__global__ void scatter_kernel(const float* __restrict__ h, float* __restrict__ agg,
                               int E, int C, int vshift) {
    long long idx = (long long)blockIdx.x * blockDim.x + threadIdx.x;
    int vecs = C >> 2;
    long long total = (long long)E * vecs;
    if (idx >= total) return;
    int e = (int)(idx >> vshift);
    int v = (int)(idx & (vecs - 1));
    int s = g_src[e];
    int d = g_dst[e];
    float nrm = g_enorm[e];
    float4 hv = *(const float4*)(h + (size_t)s * C + v * 4);
    float4 m = make_float4(hv.x * nrm, hv.y * nrm, hv.z * nrm, hv.w * nrm);
    atomicAdd((float4*)(agg + (size_t)d * C + v * 4), m);  // sm_90+ vector RED
}

// ---------------- epilogue: out = [relu](agg + h*dis^2 + b) ----------------
__global__ void epilogue_kernel(const float* __restrict__ agg, const float* __restrict__ h,
                                const float* __restrict__ b, float* __restrict__ out,
                                int C, int vshift, int relu) {
    int idx = blockIdx.x * blockDim.x + threadIdx.x;
    int vecs = C >> 2;
    if (idx >= N_NODES * vecs) return;
    int i = idx >> vshift;
    int v = idx & (vecs - 1);
    float s = g_dis[i];
    s = s * s;
    float4 av = ((const float4*)(agg + (size_t)i * C))[v];
    float4 hv = ((const float4*)(h + (size_t)i * C))[v];
    float4 bv = ((const float4*)b)[v];
    float4 o;
    o.x = fmaf(hv.x, s, av.x) + bv.x;
    o.y = fmaf(hv.y, s, av.y) + bv.y;
    o.z = fmaf(hv.z, s, av.z) + bv.z;
    o.w = fmaf(hv.w, s, av.w) + bv.w;
    if (relu) {
        o.x = fmaxf(o.x, 0.f); o.y = fmaxf(o.y, 0.f);
        o.z = fmaxf(o.z, 0.f); o.w = fmaxf(o.w, 0.f);
    }
    ((float4*)(out + (size_t)i * C))[v] = o;
}

// ---------------- driver ----------------
static inline int cdiv(long long a, long long b) { return (int)((a + b - 1) / b); }

extern "C" void kernel_launch(void* const* d_in, const int* in_sizes, int n_in,
                              void* d_out, int out_size) {
    const float* x  = (const float*)d_in[0];
    const float* W1 = (const float*)d_in[1];
    const float* b1 = (const float*)d_in[2];
    const float* W2 = (const float*)d_in[3];
    const float* b2 = (const float*)d_in[4];
    const float* W3 = (const float*)d_in[5];
    const float* b3 = (const float*)d_in[6];
    const int*   ei = (const int*)d_in[7];   // int32: JAX w/o x64 downcasts int64
    int E = in_sizes[7] / 2;
    float* out = (float*)d_out;

    float *h, *agg, *t;
    cudaGetSymbolAddress((void**)&h,   g_h);
    cudaGetSymbolAddress((void**)&agg, g_agg);
    cudaGetSymbolAddress((void**)&t,   g_t);

    const int TPB = 256;

    // ---- norm precompute (shared across all 3 layers) ----
    deg_init_kernel<<<cdiv(N_NODES, TPB), TPB>>>();
    deg_count_kernel<<<cdiv(E, TPB), TPB>>>(ei, E);
    dis_kernel<<<cdiv(N_NODES, TPB), TPB>>>();
    prep_edges_kernel<<<cdiv(E, TPB), TPB>>>(ei, E);

    // ---- layer 1: 256 -> 256, relu ----
    {
        int N = 256, K = 256;
        dim3 grid(N / 64, cdiv(N_NODES, 64));
        gemm_kernel<<<grid, 256>>>(x, W1, h, N_NODES, N, K);
        int n4 = N_NODES * N / 4;
        zero_kernel<<<cdiv(n4, TPB), TPB>>>(agg, n4);
        scatter_kernel<<<cdiv((long long)E * (N / 4), TPB), TPB>>>(h, agg, E, N, 6);
        epilogue_kernel<<<cdiv(n4, TPB), TPB>>>(agg, h, b1, t, N, 6, 1);
    }
    // ---- layer 2: 256 -> 128, relu ----
    {
        int N = 128, K = 256;
        dim3 grid(N / 64, cdiv(N_NODES, 64));
        gemm_kernel<<<grid, 256>>>(t, W2, h, N_NODES, N, K);
        int n4 = N_NODES * N / 4;
        zero_kernel<<<cdiv(n4, TPB), TPB>>>(agg, n4);
        scatter_kernel<<<cdiv((long long)E * (N / 4), TPB), TPB>>>(h, agg, E, N, 5);
        epilogue_kernel<<<cdiv(n4, TPB), TPB>>>(agg, h, b2, t, N, 5, 1);
    }
    // ---- layer 3: 128 -> 64, no relu, straight to d_out ----
    {
        int N = 64, K = 128;
        dim3 grid(N / 64, cdiv(N_NODES, 64));
        gemm_kernel<<<grid, 256>>>(t, W3, h, N_NODES, N, K);
        int n4 = N_NODES * N / 4;
        zero_kernel<<<cdiv(n4, TPB), TPB>>>(agg, n4);
        scatter_kernel<<<cdiv((long long)E * (N / 4), TPB), TPB>>>(h, agg, E, N, 4);
        epilogue_kernel<<<cdiv(n4, TPB), TPB>>>(agg, h, b3, out, N, 4, 0);
    }
}

// round 3
// speedup vs baseline: 1.0568x; 1.0568x over previous
#include <cuda_runtime.h>

#define N_NODES 20000
#define MAXC 256
#define MAXE 360000

// ---------------- scratch ----------------
__device__ int   g_indeg[N_NODES];
__device__ int   g_fill[N_NODES];
__device__ int   g_row_off[N_NODES];
__device__ float g_dis[N_NODES];
__device__ int   g_csr_src[MAXE];
__device__ float g_csr_norm[MAXE];
__device__ float g_h[(size_t)N_NODES * MAXC];    // GEMM output (pre-aggregation)
__device__ float g_t[(size_t)N_NODES * MAXC];    // layer activation

// ---------------- CSR build ----------------
__global__ void zero_counts_kernel() {
    int i = blockIdx.x * blockDim.x + threadIdx.x;
    if (i < N_NODES) { g_indeg[i] = 0; g_fill[i] = 0; }
}

__global__ void count_kernel(const int* __restrict__ ei, int E) {
    int e = blockIdx.x * blockDim.x + threadIdx.x;
    if (e < E) atomicAdd(&g_indeg[ei[E + e]], 1);
}

__global__ void dis_kernel() {
    int i = blockIdx.x * blockDim.x + threadIdx.x;
    if (i < N_NODES) g_dis[i] = rsqrtf((float)g_indeg[i] + 1.0f);  // +1 self-loop
}

// single-block exclusive scan of g_indeg -> g_row_off (1024 threads x 20 elems)
__global__ void scan_kernel() {
    __shared__ int part[1024];
    int t = threadIdx.x;
    const int CH = 20;
    int base = t * CH;
    int sum = 0;
    #pragma unroll
    for (int i = 0; i < CH; i++) {
        int idx = base + i;
        if (idx < N_NODES) sum += g_indeg[idx];
    }
    part[t] = sum;
    __syncthreads();
    for (int off = 1; off < 1024; off <<= 1) {
        int v = (t >= off) ? part[t - off] : 0;
        __syncthreads();
        part[t] += v;
        __syncthreads();
    }
    int run = (t == 0) ? 0 : part[t - 1];
    for (int i = 0; i < CH; i++) {
        int idx = base + i;
        if (idx < N_NODES) { g_row_off[idx] = run; run += g_indeg[idx]; }
    }
}

__global__ void fill_kernel(const int* __restrict__ ei, int E) {
    int e = blockIdx.x * blockDim.x + threadIdx.x;
    if (e < E) {
        int s = ei[e];
        int d = ei[E + e];
        int pos = g_row_off[d] + atomicAdd(&g_fill[d], 1);
        g_csr_src[pos] = s;
        g_csr_norm[pos] = g_dis[s] * g_dis[d];
    }
}

// ---------------- GEMM: C[M,N] = A[M,K] @ B[K,N] ----------------
// BM=128, BN=64, BK=16, 256 threads, 8x4 micro-tile.
__global__ void gemm_kernel(const float* __restrict__ A, const float* __restrict__ B,
                            float* __restrict__ C, int M, int N, int K) {
    const int BM = 128, BN = 64, BK = 16;
    __shared__ float As[BK][BM];
    __shared__ float Bs[BK][BN];

    int tid = threadIdx.x;
    int brow = blockIdx.y * BM;
    int bcol = blockIdx.x * BN;
    int ty = tid >> 4;   // 0..15 -> rows ty*8..ty*8+7
    int tx = tid & 15;   // 0..15 -> cols tx*4..tx*4+3

    float acc[8][4] = {};

    for (int k0 = 0; k0 < K; k0 += BK) {
        #pragma unroll
        for (int i = 0; i < 8; i++) {                 // A: 128x16
            int lin = tid + i * 256;
            int m = lin >> 4;
            int k = lin & 15;
            int gr = brow + m;
            As[k][m] = (gr < M) ? A[(size_t)gr * K + k0 + k] : 0.0f;
        }
        #pragma unroll
        for (int i = 0; i < 4; i++) {                 // B: 16x64
            int lin = tid + i * 256;
            int k = lin >> 6;
            int n = lin & 63;
            Bs[k][n] = B[(size_t)(k0 + k) * N + bcol + n];
        }
        __syncthreads();

        #pragma unroll
        for (int k = 0; k < BK; k++) {
            float4 b4 = *(const float4*)&Bs[k][tx * 4];
            float br[4] = {b4.x, b4.y, b4.z, b4.w};
            float4 a0 = *(const float4*)&As[k][ty * 8];
            float4 a1 = *(const float4*)&As[k][ty * 8 + 4];
            float ar[8] = {a0.x, a0.y, a0.z, a0.w, a1.x, a1.y, a1.z, a1.w};
            #pragma unroll
            for (int i = 0; i < 8; i++)
                #pragma unroll
                for (int j = 0; j < 4; j++)
                    acc[i][j] = fmaf(ar[i], br[j], acc[i][j]);
        }
        __syncthreads();
    }

    #pragma unroll
    for (int i = 0; i < 8; i++) {
        int gr = brow + ty * 8 + i;
        if (gr < M) {
            float4 v = make_float4(acc[i][0], acc[i][1], acc[i][2], acc[i][3]);
            *(float4*)&C[(size_t)gr * N + bcol + tx * 4] = v;
        }
    }
}

// ---------------- fused aggregate + self-loop + bias (+relu) ----------------
// one block per node, C threads; gathers CSR in-edges, accumulates in registers
template<int C, bool RELU>
__global__ void aggregate_kernel(const float* __restrict__ h,
                                 const float* __restrict__ bias,
                                 float* __restrict__ out) {
    int node = blockIdx.x;
    int tid = threadIdx.x;
    float dd = g_dis[node];
    float acc = h[(size_t)node * C + tid] * (dd * dd);   // self-loop
    int beg = g_row_off[node];
    int end = beg + g_indeg[node];
    int p = beg;
    for (; p + 4 <= end; p += 4) {
        int s0 = g_csr_src[p],   s1 = g_csr_src[p+1];
        int s2 = g_csr_src[p+2], s3 = g_csr_src[p+3];
        float w0 = g_csr_norm[p],   w1 = g_csr_norm[p+1];
        float w2 = g_csr_norm[p+2], w3 = g_csr_norm[p+3];
        float v0 = h[(size_t)s0 * C + tid];
        float v1 = h[(size_t)s1 * C + tid];
        float v2 = h[(size_t)s2 * C + tid];
        float v3 = h[(size_t)s3 * C + tid];
        acc = fmaf(v0, w0, acc);
        acc = fmaf(v1, w1, acc);
        acc = fmaf(v2, w2, acc);
        acc = fmaf(v3, w3, acc);
    }
    for (; p < end; ++p)
        acc = fmaf(h[(size_t)g_csr_src[p] * C + tid], g_csr_norm[p], acc);
    acc += bias[tid];
    if (RELU) acc = fmaxf(acc, 0.0f);
    out[(size_t)node * C + tid] = acc;
}

// ---------------- driver ----------------
static inline int cdiv(long long a, long long b) { return (int)((a + b - 1) / b); }

extern "C" void kernel_launch(void* const* d_in, const int* in_sizes, int n_in,
                              void* d_out, int out_size) {
    const float* x  = (const float*)d_in[0];
    const float* W1 = (const float*)d_in[1];
    const float* b1 = (const float*)d_in[2];
    const float* W2 = (const float*)d_in[3];
    const float* b2 = (const float*)d_in[4];
    const float* W3 = (const float*)d_in[5];
    const float* b3 = (const float*)d_in[6];
    const int*   ei = (const int*)d_in[7];   // int32 (JAX default dtype demotion)
    int E = in_sizes[7] / 2;
    float* out = (float*)d_out;

    float *h, *t;
    cudaGetSymbolAddress((void**)&h, g_h);
    cudaGetSymbolAddress((void**)&t, g_t);

    const int TPB = 256;

    // ---- CSR + norm build (shared across all 3 layers) ----
    zero_counts_kernel<<<cdiv(N_NODES, TPB), TPB>>>();
    count_kernel<<<cdiv(E, TPB), TPB>>>(ei, E);
    dis_kernel<<<cdiv(N_NODES, TPB), TPB>>>();
    scan_kernel<<<1, 1024>>>();
    fill_kernel<<<cdiv(E, TPB), TPB>>>(ei, E);

    // ---- layer 1: 256 -> 256, relu ----
    {
        dim3 grid(256 / 64, cdiv(N_NODES, 128));
        gemm_kernel<<<grid, 256>>>(x, W1, h, N_NODES, 256, 256);
        aggregate_kernel<256, true><<<N_NODES, 256>>>(h, b1, t);
    }
    // ---- layer 2: 256 -> 128, relu ----
    {
        dim3 grid(128 / 64, cdiv(N_NODES, 128));
        gemm_kernel<<<grid, 256>>>(t, W2, h, N_NODES, 128, 256);
        aggregate_kernel<128, true><<<N_NODES, 128>>>(h, b2, t);
    }
    // ---- layer 3: 128 -> 64, no relu ----
    {
        dim3 grid(64 / 64, cdiv(N_NODES, 128));
        gemm_kernel<<<grid, 256>>>(t, W3, h, N_NODES, 64, 128);
        aggregate_kernel<64, false><<<N_NODES, 64>>>(h, b3, out);
    }
}

// round 4
// speedup vs baseline: 1.2777x; 1.2090x over previous
#include <cuda_runtime.h>

#define N_NODES 20000
#define MAXC 256
#define MAXE 360000

// ---------------- scratch ----------------
__device__ int   g_indeg[N_NODES];
__device__ int   g_fill[N_NODES];
__device__ int   g_row_off[N_NODES];
__device__ float g_dis[N_NODES];
__device__ int   g_csr_src[MAXE];
__device__ float g_h[(size_t)N_NODES * MAXC];    // scaled GEMM output
__device__ float g_t[(size_t)N_NODES * MAXC];    // layer activation

// ---------------- CSR build ----------------
__global__ void zero_counts_kernel() {
    int i = blockIdx.x * blockDim.x + threadIdx.x;
    if (i < N_NODES) { g_indeg[i] = 0; g_fill[i] = 0; }
}

__global__ void count_kernel(const int* __restrict__ ei, int E) {
    int e = blockIdx.x * blockDim.x + threadIdx.x;
    if (e < E) atomicAdd(&g_indeg[ei[E + e]], 1);
}

// warp-shuffle exclusive scan of g_indeg -> g_row_off; also computes g_dis
__global__ void scan_kernel() {
    __shared__ int wsum[32];
    const int CH = 20;
    int t = threadIdx.x;              // 1024 threads
    int lane = t & 31, wid = t >> 5;
    int base = t * CH;
    int local[CH];
    int s = 0;
    #pragma unroll
    for (int i = 0; i < CH; i++) {
        int idx = base + i;
        int v = (idx < N_NODES) ? g_indeg[idx] : 0;
        local[i] = v;
        s += v;
    }
    // intra-warp inclusive scan of per-thread sums
    int v = s;
    #pragma unroll
    for (int off = 1; off < 32; off <<= 1) {
        int n = __shfl_up_sync(0xffffffffu, v, off);
        if (lane >= off) v += n;
    }
    if (lane == 31) wsum[wid] = v;
    __syncthreads();
    if (wid == 0) {
        int w = wsum[lane];
        #pragma unroll
        for (int off = 1; off < 32; off <<= 1) {
            int n = __shfl_up_sync(0xffffffffu, w, off);
            if (lane >= off) w += n;
        }
        wsum[lane] = w;   // inclusive warp prefix
    }
    __syncthreads();
    int warpoff = (wid == 0) ? 0 : wsum[wid - 1];
    int run = warpoff + v - s;        // exclusive prefix for this thread
    #pragma unroll
    for (int i = 0; i < CH; i++) {
        int idx = base + i;
        if (idx < N_NODES) {
            g_row_off[idx] = run;
            run += local[i];
            g_dis[idx] = rsqrtf((float)local[i] + 1.0f);   // +1 self-loop
        }
    }
}

__global__ void fill_kernel(const int* __restrict__ ei, int E) {
    int e = blockIdx.x * blockDim.x + threadIdx.x;
    if (e < E) {
        int s = ei[e];
        int d = ei[E + e];
        int pos = g_row_off[d] + atomicAdd(&g_fill[d], 1);
        g_csr_src[pos] = s;
    }
}

// ---------------- GEMM: C[M,N] = rowscale[m] * (A[M,K] @ B[K,N]) ----------------
// BM=128, BN=64, BK=16, 256 threads, 8x4 micro-tile, double-buffered smem.
// A-tile padded to stride 132 floats: kills 16-way store bank conflict,
// keeps 16B alignment for float4 reads.
__global__ void gemm_kernel(const float* __restrict__ A, const float* __restrict__ B,
                            const float* __restrict__ rowscale,
                            float* __restrict__ C, int M, int N, int K) {
    const int BM = 128, BN = 64, BK = 16, PAD = 132;
    __shared__ float As[2][BK][PAD];
    __shared__ float Bs[2][BK][BN];

    int tid = threadIdx.x;
    int brow = blockIdx.y * BM;
    int bcol = blockIdx.x * BN;
    int ty = tid >> 4;   // 0..15 -> rows ty*8..ty*8+7
    int tx = tid & 15;   // 0..15 -> cols tx*4..tx*4+3

    float acc[8][4] = {};
    float ra[8], rb[4];

    // prologue: tile 0
    #pragma unroll
    for (int i = 0; i < 8; i++) {
        int lin = tid + i * 256;
        int m = lin >> 4, k = lin & 15;
        int gr = brow + m;
        As[0][k][m] = (gr < M) ? A[(size_t)gr * K + k] : 0.0f;
    }
    #pragma unroll
    for (int i = 0; i < 4; i++) {
        int lin = tid + i * 256;
        int k = lin >> 6, n = lin & 63;
        Bs[0][k][n] = B[(size_t)k * N + bcol + n];
    }
    __syncthreads();

    int KT = K / BK;
    int cur = 0;
    for (int kt = 0; kt < KT; kt++) {
        bool more = (kt + 1 < KT);
        if (more) {
            int k0n = (kt + 1) * BK;
            #pragma unroll
            for (int i = 0; i < 8; i++) {
                int lin = tid + i * 256;
                int m = lin >> 4, k = lin & 15;
                int gr = brow + m;
                ra[i] = (gr < M) ? A[(size_t)gr * K + k0n + k] : 0.0f;
            }
            #pragma unroll
            for (int i = 0; i < 4; i++) {
                int lin = tid + i * 256;
                int k = lin >> 6, n = lin & 63;
                rb[i] = B[(size_t)(k0n + k) * N + bcol + n];
            }
        }
        #pragma unroll
        for (int k = 0; k < BK; k++) {
            float4 b4 = *(const float4*)&Bs[cur][k][tx * 4];
            float br[4] = {b4.x, b4.y, b4.z, b4.w};
            float4 a0 = *(const float4*)&As[cur][k][ty * 8];
            float4 a1 = *(const float4*)&As[cur][k][ty * 8 + 4];
            float ar[8] = {a0.x, a0.y, a0.z, a0.w, a1.x, a1.y, a1.z, a1.w};
            #pragma unroll
            for (int i = 0; i < 8; i++)
                #pragma unroll
                for (int j = 0; j < 4; j++)
                    acc[i][j] = fmaf(ar[i], br[j], acc[i][j]);
        }
        if (more) {
            int nxt = cur ^ 1;
            #pragma unroll
            for (int i = 0; i < 8; i++) {
                int lin = tid + i * 256;
                int m = lin >> 4, k = lin & 15;
                As[nxt][k][m] = ra[i];
            }
            #pragma unroll
            for (int i = 0; i < 4; i++) {
                int lin = tid + i * 256;
                int k = lin >> 6, n = lin & 63;
                Bs[nxt][k][n] = rb[i];
            }
            __syncthreads();
            cur = nxt;
        }
    }

    #pragma unroll
    for (int i = 0; i < 8; i++) {
        int gr = brow + ty * 8 + i;
        if (gr < M) {
            float sc = rowscale[gr];
            float4 v = make_float4(acc[i][0] * sc, acc[i][1] * sc,
                                   acc[i][2] * sc, acc[i][3] * sc);
            *(float4*)&C[(size_t)gr * N + bcol + tx * 4] = v;
        }
    }
}

// ---------------- fused aggregate + self-loop + bias (+relu) ----------------
// h is pre-scaled by dis[row]; out[d] = relu(dis[d]*(h[d] + sum_{s in N(d)} h[s]) + b)
template<int C, bool RELU>
__global__ void aggregate_kernel(const float* __restrict__ h,
                                 const float* __restrict__ bias,
                                 float* __restrict__ out) {
    constexpr int CB = (C > 128) ? 128 : C;
    int node = blockIdx.x;
    int col = blockIdx.y * CB + threadIdx.x;
    float acc = __ldg(&h[(size_t)node * C + col]);   // self (already scaled)
    int beg = g_row_off[node];
    int end = beg + g_indeg[node];
    int p = beg;
    for (; p + 8 <= end; p += 8) {
        int s[8];
        #pragma unroll
        for (int j = 0; j < 8; j++) s[j] = g_csr_src[p + j];
        #pragma unroll
        for (int j = 0; j < 8; j++) acc += __ldg(&h[(size_t)s[j] * C + col]);
    }
    for (; p < end; ++p)
        acc += __ldg(&h[(size_t)g_csr_src[p] * C + col]);
    float r = g_dis[node] * acc + __ldg(&bias[col]);
    if (RELU) r = fmaxf(r, 0.0f);
    out[(size_t)node * C + col] = r;
}

// ---------------- driver ----------------
static inline int cdiv(long long a, long long b) { return (int)((a + b - 1) / b); }

extern "C" void kernel_launch(void* const* d_in, const int* in_sizes, int n_in,
                              void* d_out, int out_size) {
    const float* x  = (const float*)d_in[0];
    const float* W1 = (const float*)d_in[1];
    const float* b1 = (const float*)d_in[2];
    const float* W2 = (const float*)d_in[3];
    const float* b2 = (const float*)d_in[4];
    const float* W3 = (const float*)d_in[5];
    const float* b3 = (const float*)d_in[6];
    const int*   ei = (const int*)d_in[7];   // int32 (JAX default dtype demotion)
    int E = in_sizes[7] / 2;
    float* out = (float*)d_out;

    float *h, *t, *dis;
    cudaGetSymbolAddress((void**)&h,   g_h);
    cudaGetSymbolAddress((void**)&t,   g_t);
    cudaGetSymbolAddress((void**)&dis, g_dis);

    const int TPB = 256;

    // ---- CSR + norm build (shared across all 3 layers) ----
    zero_counts_kernel<<<cdiv(N_NODES, TPB), TPB>>>();
    count_kernel<<<cdiv(E, TPB), TPB>>>(ei, E);
    scan_kernel<<<1, 1024>>>();
    fill_kernel<<<cdiv(E, TPB), TPB>>>(ei, E);

    // ---- layer 1: 256 -> 256, relu ----
    {
        dim3 grid(256 / 64, cdiv(N_NODES, 128));
        gemm_kernel<<<grid, 256>>>(x, W1, dis, h, N_NODES, 256, 256);
        aggregate_kernel<256, true><<<dim3(N_NODES, 2), 128>>>(h, b1, t);
    }
    // ---- layer 2: 256 -> 128, relu ----
    {
        dim3 grid(128 / 64, cdiv(N_NODES, 128));
        gemm_kernel<<<grid, 256>>>(t, W2, dis, h, N_NODES, 128, 256);
        aggregate_kernel<128, true><<<dim3(N_NODES, 1), 128>>>(h, b2, t);
    }
    // ---- layer 3: 128 -> 64, no relu ----
    {
        dim3 grid(64 / 64, cdiv(N_NODES, 128));
        gemm_kernel<<<grid, 256>>>(t, W3, dis, h, N_NODES, 64, 128);
        aggregate_kernel<64, false><<<dim3(N_NODES, 1), 64>>>(h, b3, out);
    }
}

// round 5
// speedup vs baseline: 1.5714x; 1.2298x over previous
#include <cuda_runtime.h>
#include <cstdint>

#define N_NODES 20000
#define MAXC 256
#define MAXE 360000

// ---------------- scratch ----------------
__device__ int   g_indeg[N_NODES];
__device__ int   g_fill[N_NODES];
__device__ int   g_row_off[N_NODES];
__device__ float g_dis[N_NODES];
__device__ int   g_csr_src[MAXE];
__device__ float g_h[(size_t)N_NODES * MAXC];    // scaled GEMM output
__device__ float g_t[(size_t)N_NODES * MAXC];    // layer activation

// ---------------- CSR build ----------------
__global__ void zero_counts_kernel() {
    int i = blockIdx.x * blockDim.x + threadIdx.x;
    if (i < N_NODES) { g_indeg[i] = 0; g_fill[i] = 0; }
}

__global__ void count_kernel(const int* __restrict__ ei, int E) {
    int e = blockIdx.x * blockDim.x + threadIdx.x;
    if (e < E) atomicAdd(&g_indeg[ei[E + e]], 1);
}

// warp-shuffle exclusive scan of g_indeg -> g_row_off; also computes g_dis
__global__ void scan_kernel() {
    __shared__ int wsum[32];
    const int CH = 20;
    int t = threadIdx.x;              // 1024 threads
    int lane = t & 31, wid = t >> 5;
    int base = t * CH;
    int local[CH];
    int s = 0;
    #pragma unroll
    for (int i = 0; i < CH; i++) {
        int idx = base + i;
        int v = (idx < N_NODES) ? g_indeg[idx] : 0;
        local[i] = v;
        s += v;
    }
    int v = s;
    #pragma unroll
    for (int off = 1; off < 32; off <<= 1) {
        int n = __shfl_up_sync(0xffffffffu, v, off);
        if (lane >= off) v += n;
    }
    if (lane == 31) wsum[wid] = v;
    __syncthreads();
    if (wid == 0) {
        int w = wsum[lane];
        #pragma unroll
        for (int off = 1; off < 32; off <<= 1) {
            int n = __shfl_up_sync(0xffffffffu, w, off);
            if (lane >= off) w += n;
        }
        wsum[lane] = w;
    }
    __syncthreads();
    int warpoff = (wid == 0) ? 0 : wsum[wid - 1];
    int run = warpoff + v - s;
    #pragma unroll
    for (int i = 0; i < CH; i++) {
        int idx = base + i;
        if (idx < N_NODES) {
            g_row_off[idx] = run;
            run += local[i];
            g_dis[idx] = rsqrtf((float)local[i] + 1.0f);   // +1 self-loop
        }
    }
}

__global__ void fill_kernel(const int* __restrict__ ei, int E) {
    int e = blockIdx.x * blockDim.x + threadIdx.x;
    if (e < E) {
        int s = ei[e];
        int d = ei[E + e];
        int pos = g_row_off[d] + atomicAdd(&g_fill[d], 1);
        g_csr_src[pos] = s;
    }
}

// ---------------- TF32 tensor-core GEMM ----------------
// C[M,N] = rowscale[m] * (A[M,K] @ B[K,N]); fp32 in/out, tf32 mma.sync.
// BM=128, BN=64, BK=16. 256 threads = 8 warps (4x2); warp tile 32x32
// = 2 m-tiles x 4 n-tiles of m16n8k8. Double-buffered smem.
__device__ __forceinline__ uint32_t f2tf32(float f) {
    uint32_t r;
    asm("cvt.rna.tf32.f32 %0, %1;" : "=r"(r) : "f"(f));
    return r;
}

__global__ void gemm_tf32_kernel(const float* __restrict__ A, const float* __restrict__ B,
                                 const float* __restrict__ rowscale,
                                 float* __restrict__ C, int M, int N, int K) {
    const int BM = 128, BN = 64, BK = 16;
    __shared__ uint32_t As[2][BK][132];   // [k][m], padded
    __shared__ uint32_t Bs[2][BK][68];    // [k][n], padded

    int tid = threadIdx.x;
    int lane = tid & 31;
    int wid = tid >> 5;
    int warp_m = wid & 3;    // 0..3 -> 32-row slab
    int warp_n = wid >> 2;   // 0..1 -> 32-col slab
    int brow = blockIdx.y * BM;
    int bcol = blockIdx.x * BN;

    int g = lane >> 2;       // groupID 0..7
    int tg = lane & 3;       // thread-in-group 0..3

    float acc[2][4][4];
    #pragma unroll
    for (int i = 0; i < 2; i++)
        #pragma unroll
        for (int j = 0; j < 4; j++)
            #pragma unroll
            for (int q = 0; q < 4; q++) acc[i][j][q] = 0.0f;

    uint32_t ra[8], rb[4];

    // prologue: tile 0
    #pragma unroll
    for (int i = 0; i < 8; i++) {
        int lin = tid + i * 256;
        int m = lin >> 4, k = lin & 15;
        int gr = brow + m;
        As[0][k][m] = f2tf32((gr < M) ? A[(size_t)gr * K + k] : 0.0f);
    }
    #pragma unroll
    for (int i = 0; i < 4; i++) {
        int lin = tid + i * 256;
        int k = lin >> 6, n = lin & 63;
        Bs[0][k][n] = f2tf32(B[(size_t)k * N + bcol + n]);
    }
    __syncthreads();

    int KT = K / BK;
    int cur = 0;
    for (int kt = 0; kt < KT; kt++) {
        bool more = (kt + 1 < KT);
        if (more) {
            int k0n = (kt + 1) * BK;
            #pragma unroll
            for (int i = 0; i < 8; i++) {
                int lin = tid + i * 256;
                int m = lin >> 4, k = lin & 15;
                int gr = brow + m;
                ra[i] = f2tf32((gr < M) ? A[(size_t)gr * K + k0n + k] : 0.0f);
            }
            #pragma unroll
            for (int i = 0; i < 4; i++) {
                int lin = tid + i * 256;
                int k = lin >> 6, n = lin & 63;
                rb[i] = f2tf32(B[(size_t)(k0n + k) * N + bcol + n]);
            }
        }
        // 2 k-steps of 8
        #pragma unroll
        for (int ks = 0; ks < 2; ks++) {
            int kb = ks * 8;
            uint32_t af[2][4], bf[4][2];
            #pragma unroll
            for (int mt = 0; mt < 2; mt++) {
                int r0 = warp_m * 32 + mt * 16 + g;
                af[mt][0] = As[cur][kb + tg][r0];
                af[mt][1] = As[cur][kb + tg][r0 + 8];
                af[mt][2] = As[cur][kb + tg + 4][r0];
                af[mt][3] = As[cur][kb + tg + 4][r0 + 8];
            }
            #pragma unroll
            for (int nt = 0; nt < 4; nt++) {
                int c0 = warp_n * 32 + nt * 8 + g;
                bf[nt][0] = Bs[cur][kb + tg][c0];
                bf[nt][1] = Bs[cur][kb + tg + 4][c0];
            }
            #pragma unroll
            for (int mt = 0; mt < 2; mt++)
                #pragma unroll
                for (int nt = 0; nt < 4; nt++) {
                    asm volatile(
                        "mma.sync.aligned.m16n8k8.row.col.f32.tf32.tf32.f32 "
                        "{%0,%1,%2,%3}, {%4,%5,%6,%7}, {%8,%9}, {%0,%1,%2,%3};"
                        : "+f"(acc[mt][nt][0]), "+f"(acc[mt][nt][1]),
                          "+f"(acc[mt][nt][2]), "+f"(acc[mt][nt][3])
                        : "r"(af[mt][0]), "r"(af[mt][1]), "r"(af[mt][2]), "r"(af[mt][3]),
                          "r"(bf[nt][0]), "r"(bf[nt][1]));
                }
        }
        if (more) {
            int nxt = cur ^ 1;
            #pragma unroll
            for (int i = 0; i < 8; i++) {
                int lin = tid + i * 256;
                int m = lin >> 4, k = lin & 15;
                As[nxt][k][m] = ra[i];
            }
            #pragma unroll
            for (int i = 0; i < 4; i++) {
                int lin = tid + i * 256;
                int k = lin >> 6, n = lin & 63;
                Bs[nxt][k][n] = rb[i];
            }
            __syncthreads();
            cur = nxt;
        }
    }

    // epilogue: rowscale + store (c0,c1) and (c2,c3) as float2
    #pragma unroll
    for (int mt = 0; mt < 2; mt++) {
        int r0 = brow + warp_m * 32 + mt * 16 + g;
        int r1 = r0 + 8;
        float s0 = (r0 < M) ? rowscale[r0] : 0.0f;
        float s1 = (r1 < M) ? rowscale[r1] : 0.0f;
        #pragma unroll
        for (int nt = 0; nt < 4; nt++) {
            int cc = bcol + warp_n * 32 + nt * 8 + 2 * tg;
            if (r0 < M) {
                float2 v = make_float2(acc[mt][nt][0] * s0, acc[mt][nt][1] * s0);
                *(float2*)&C[(size_t)r0 * N + cc] = v;
            }
            if (r1 < M) {
                float2 v = make_float2(acc[mt][nt][2] * s1, acc[mt][nt][3] * s1);
                *(float2*)&C[(size_t)r1 * N + cc] = v;
            }
        }
    }
}

// ---------------- fused aggregate + self-loop + bias (+relu) ----------------
template<int C, bool RELU>
__global__ void aggregate_kernel(const float* __restrict__ h,
                                 const float* __restrict__ bias,
                                 float* __restrict__ out) {
    constexpr int CB = (C > 128) ? 128 : C;
    int node = blockIdx.x;
    int col = blockIdx.y * CB + threadIdx.x;
    float acc = __ldg(&h[(size_t)node * C + col]);   // self (already scaled)
    int beg = g_row_off[node];
    int end = beg + g_indeg[node];
    int p = beg;
    for (; p + 8 <= end; p += 8) {
        int s[8];
        #pragma unroll
        for (int j = 0; j < 8; j++) s[j] = g_csr_src[p + j];
        #pragma unroll
        for (int j = 0; j < 8; j++) acc += __ldg(&h[(size_t)s[j] * C + col]);
    }
    for (; p < end; ++p)
        acc += __ldg(&h[(size_t)g_csr_src[p] * C + col]);
    float r = g_dis[node] * acc + __ldg(&bias[col]);
    if (RELU) r = fmaxf(r, 0.0f);
    out[(size_t)node * C + col] = r;
}

// ---------------- driver ----------------
static inline int cdiv(long long a, long long b) { return (int)((a + b - 1) / b); }

extern "C" void kernel_launch(void* const* d_in, const int* in_sizes, int n_in,
                              void* d_out, int out_size) {
    const float* x  = (const float*)d_in[0];
    const float* W1 = (const float*)d_in[1];
    const float* b1 = (const float*)d_in[2];
    const float* W2 = (const float*)d_in[3];
    const float* b2 = (const float*)d_in[4];
    const float* W3 = (const float*)d_in[5];
    const float* b3 = (const float*)d_in[6];
    const int*   ei = (const int*)d_in[7];   // int32 (JAX default dtype demotion)
    int E = in_sizes[7] / 2;
    float* out = (float*)d_out;

    float *h, *t, *dis;
    cudaGetSymbolAddress((void**)&h,   g_h);
    cudaGetSymbolAddress((void**)&t,   g_t);
    cudaGetSymbolAddress((void**)&dis, g_dis);

    const int TPB = 256;

    // ---- CSR + norm build (shared across all 3 layers) ----
    zero_counts_kernel<<<cdiv(N_NODES, TPB), TPB>>>();
    count_kernel<<<cdiv(E, TPB), TPB>>>(ei, E);
    scan_kernel<<<1, 1024>>>();
    fill_kernel<<<cdiv(E, TPB), TPB>>>(ei, E);

    // ---- layer 1: 256 -> 256, relu ----
    {
        dim3 grid(256 / 64, cdiv(N_NODES, 128));
        gemm_tf32_kernel<<<grid, 256>>>(x, W1, dis, h, N_NODES, 256, 256);
        aggregate_kernel<256, true><<<dim3(N_NODES, 2), 128>>>(h, b1, t);
    }
    // ---- layer 2: 256 -> 128, relu ----
    {
        dim3 grid(128 / 64, cdiv(N_NODES, 128));
        gemm_tf32_kernel<<<grid, 256>>>(t, W2, dis, h, N_NODES, 128, 256);
        aggregate_kernel<128, true><<<dim3(N_NODES, 1), 128>>>(h, b2, t);
    }
    // ---- layer 3: 128 -> 64, no relu ----
    {
        dim3 grid(64 / 64, cdiv(N_NODES, 128));
        gemm_tf32_kernel<<<grid, 256>>>(t, W3, dis, h, N_NODES, 64, 128);
        aggregate_kernel<64, false><<<dim3(N_NODES, 1), 64>>>(h, b3, out);
    }
}

// round 6
// speedup vs baseline: 1.8090x; 1.1512x over previous
#include <cuda_runtime.h>
#include <cstdint>

#define N_NODES 20000
#define MAXC 256
#define MAXE 360000

// ---------------- scratch ----------------
__device__ int   g_indeg[N_NODES];
__device__ int   g_fill[N_NODES];
__device__ int   g_row_off[N_NODES];
__device__ float g_dis[N_NODES];
__device__ int   g_csr_src[MAXE];
__device__ float g_h[(size_t)N_NODES * MAXC];    // scaled GEMM output
__device__ float g_t[(size_t)N_NODES * MAXC];    // layer activation

// ---------------- CSR build ----------------
__global__ void zero_counts_kernel() {
    int i = blockIdx.x * blockDim.x + threadIdx.x;
    if (i < N_NODES) { g_indeg[i] = 0; g_fill[i] = 0; }
}

__global__ void count_kernel(const int* __restrict__ ei, int E) {
    int e = blockIdx.x * blockDim.x + threadIdx.x;
    if (e < E) atomicAdd(&g_indeg[ei[E + e]], 1);
}

// warp-shuffle exclusive scan of g_indeg -> g_row_off; also computes g_dis
__global__ void scan_kernel() {
    __shared__ int wsum[32];
    const int CH = 20;
    int t = threadIdx.x;              // 1024 threads
    int lane = t & 31, wid = t >> 5;
    int base = t * CH;
    int local[CH];
    int s = 0;
    #pragma unroll
    for (int i = 0; i < CH; i++) {
        int idx = base + i;
        int v = (idx < N_NODES) ? g_indeg[idx] : 0;
        local[i] = v;
        s += v;
    }
    int v = s;
    #pragma unroll
    for (int off = 1; off < 32; off <<= 1) {
        int n = __shfl_up_sync(0xffffffffu, v, off);
        if (lane >= off) v += n;
    }
    if (lane == 31) wsum[wid] = v;
    __syncthreads();
    if (wid == 0) {
        int w = wsum[lane];
        #pragma unroll
        for (int off = 1; off < 32; off <<= 1) {
            int n = __shfl_up_sync(0xffffffffu, w, off);
            if (lane >= off) w += n;
        }
        wsum[lane] = w;
    }
    __syncthreads();
    int warpoff = (wid == 0) ? 0 : wsum[wid - 1];
    int run = warpoff + v - s;
    #pragma unroll
    for (int i = 0; i < CH; i++) {
        int idx = base + i;
        if (idx < N_NODES) {
            g_row_off[idx] = run;
            run += local[i];
            g_dis[idx] = rsqrtf((float)local[i] + 1.0f);   // +1 self-loop
        }
    }
}

__global__ void fill_kernel(const int* __restrict__ ei, int E) {
    int e = blockIdx.x * blockDim.x + threadIdx.x;
    if (e < E) {
        int s = ei[e];
        int d = ei[E + e];
        int pos = g_row_off[d] + atomicAdd(&g_fill[d], 1);
        g_csr_src[pos] = s;
    }
}

// ---------------- TF32 tensor-core GEMM ----------------
// C[M,N] = rowscale[m] * (A[M,K] @ B[K,N]); fp32 in/out, tf32 mma.sync.
__device__ __forceinline__ uint32_t f2tf32(float f) {
    uint32_t r;
    asm("cvt.rna.tf32.f32 %0, %1;" : "=r"(r) : "f"(f));
    return r;
}

__global__ void gemm_tf32_kernel(const float* __restrict__ A, const float* __restrict__ B,
                                 const float* __restrict__ rowscale,
                                 float* __restrict__ C, int M, int N, int K) {
    const int BM = 128, BN = 64, BK = 16;
    __shared__ uint32_t As[2][BK][132];   // [k][m], padded
    __shared__ uint32_t Bs[2][BK][68];    // [k][n], padded

    int tid = threadIdx.x;
    int lane = tid & 31;
    int wid = tid >> 5;
    int warp_m = wid & 3;
    int warp_n = wid >> 2;
    int brow = blockIdx.y * BM;
    int bcol = blockIdx.x * BN;

    int g = lane >> 2;
    int tg = lane & 3;

    float acc[2][4][4];
    #pragma unroll
    for (int i = 0; i < 2; i++)
        #pragma unroll
        for (int j = 0; j < 4; j++)
            #pragma unroll
            for (int q = 0; q < 4; q++) acc[i][j][q] = 0.0f;

    uint32_t ra[8], rb[4];

    #pragma unroll
    for (int i = 0; i < 8; i++) {
        int lin = tid + i * 256;
        int m = lin >> 4, k = lin & 15;
        int gr = brow + m;
        As[0][k][m] = f2tf32((gr < M) ? A[(size_t)gr * K + k] : 0.0f);
    }
    #pragma unroll
    for (int i = 0; i < 4; i++) {
        int lin = tid + i * 256;
        int k = lin >> 6, n = lin & 63;
        Bs[0][k][n] = f2tf32(B[(size_t)k * N + bcol + n]);
    }
    __syncthreads();

    int KT = K / BK;
    int cur = 0;
    for (int kt = 0; kt < KT; kt++) {
        bool more = (kt + 1 < KT);
        if (more) {
            int k0n = (kt + 1) * BK;
            #pragma unroll
            for (int i = 0; i < 8; i++) {
                int lin = tid + i * 256;
                int m = lin >> 4, k = lin & 15;
                int gr = brow + m;
                ra[i] = f2tf32((gr < M) ? A[(size_t)gr * K + k0n + k] : 0.0f);
            }
            #pragma unroll
            for (int i = 0; i < 4; i++) {
                int lin = tid + i * 256;
                int k = lin >> 6, n = lin & 63;
                rb[i] = f2tf32(B[(size_t)(k0n + k) * N + bcol + n]);
            }
        }
        #pragma unroll
        for (int ks = 0; ks < 2; ks++) {
            int kb = ks * 8;
            uint32_t af[2][4], bf[4][2];
            #pragma unroll
            for (int mt = 0; mt < 2; mt++) {
                int r0 = warp_m * 32 + mt * 16 + g;
                af[mt][0] = As[cur][kb + tg][r0];
                af[mt][1] = As[cur][kb + tg][r0 + 8];
                af[mt][2] = As[cur][kb + tg + 4][r0];
                af[mt][3] = As[cur][kb + tg + 4][r0 + 8];
            }
            #pragma unroll
            for (int nt = 0; nt < 4; nt++) {
                int c0 = warp_n * 32 + nt * 8 + g;
                bf[nt][0] = Bs[cur][kb + tg][c0];
                bf[nt][1] = Bs[cur][kb + tg + 4][c0];
            }
            #pragma unroll
            for (int mt = 0; mt < 2; mt++)
                #pragma unroll
                for (int nt = 0; nt < 4; nt++) {
                    asm volatile(
                        "mma.sync.aligned.m16n8k8.row.col.f32.tf32.tf32.f32 "
                        "{%0,%1,%2,%3}, {%4,%5,%6,%7}, {%8,%9}, {%0,%1,%2,%3};"
                        : "+f"(acc[mt][nt][0]), "+f"(acc[mt][nt][1]),
                          "+f"(acc[mt][nt][2]), "+f"(acc[mt][nt][3])
                        : "r"(af[mt][0]), "r"(af[mt][1]), "r"(af[mt][2]), "r"(af[mt][3]),
                          "r"(bf[nt][0]), "r"(bf[nt][1]));
                }
        }
        if (more) {
            int nxt = cur ^ 1;
            #pragma unroll
            for (int i = 0; i < 8; i++) {
                int lin = tid + i * 256;
                int m = lin >> 4, k = lin & 15;
                As[nxt][k][m] = ra[i];
            }
            #pragma unroll
            for (int i = 0; i < 4; i++) {
                int lin = tid + i * 256;
                int k = lin >> 6, n = lin & 63;
                Bs[nxt][k][n] = rb[i];
            }
            __syncthreads();
            cur = nxt;
        }
    }

    #pragma unroll
    for (int mt = 0; mt < 2; mt++) {
        int r0 = brow + warp_m * 32 + mt * 16 + g;
        int r1 = r0 + 8;
        float s0 = (r0 < M) ? rowscale[r0] : 0.0f;
        float s1 = (r1 < M) ? rowscale[r1] : 0.0f;
        #pragma unroll
        for (int nt = 0; nt < 4; nt++) {
            int cc = bcol + warp_n * 32 + nt * 8 + 2 * tg;
            if (r0 < M) {
                float2 v = make_float2(acc[mt][nt][0] * s0, acc[mt][nt][1] * s0);
                *(float2*)&C[(size_t)r0 * N + cc] = v;
            }
            if (r1 < M) {
                float2 v = make_float2(acc[mt][nt][2] * s1, acc[mt][nt][3] * s1);
                *(float2*)&C[(size_t)r1 * N + cc] = v;
            }
        }
    }
}

// ---------------- fused aggregate + self-loop + bias (+relu), float4 lanes ----------------
// h pre-scaled by dis[row]; out[d] = relu(dis[d]*(h[d] + sum_{s in N(d)} h[s]) + b)
template<int C, bool RELU>
__global__ void aggregate_kernel(const float* __restrict__ h,
                                 const float* __restrict__ bias,
                                 float* __restrict__ out) {
    constexpr int TPN = C / 4;            // threads per node (float4 lanes)
    constexpr int NPB = 128 / TPN;        // nodes per block
    int local = threadIdx.x / TPN;
    int c4 = threadIdx.x % TPN;
    int node = blockIdx.x * NPB + local;
    if (node >= N_NODES) return;

    const float4* h4 = (const float4*)h;
    const size_t S = C / 4;
    float4 a = __ldg(&h4[(size_t)node * S + c4]);   // self (already scaled)
    float accx = a.x, accy = a.y, accz = a.z, accw = a.w;

    int beg = g_row_off[node];
    int end = beg + g_indeg[node];
    int p = beg;
    for (; p + 4 <= end; p += 4) {
        int s0 = g_csr_src[p],   s1 = g_csr_src[p+1];
        int s2 = g_csr_src[p+2], s3 = g_csr_src[p+3];
        float4 v0 = __ldg(&h4[(size_t)s0 * S + c4]);
        float4 v1 = __ldg(&h4[(size_t)s1 * S + c4]);
        float4 v2 = __ldg(&h4[(size_t)s2 * S + c4]);
        float4 v3 = __ldg(&h4[(size_t)s3 * S + c4]);
        accx += (v0.x + v1.x) + (v2.x + v3.x);
        accy += (v0.y + v1.y) + (v2.y + v3.y);
        accz += (v0.z + v1.z) + (v2.z + v3.z);
        accw += (v0.w + v1.w) + (v2.w + v3.w);
    }
    for (; p < end; ++p) {
        float4 v = __ldg(&h4[(size_t)g_csr_src[p] * S + c4]);
        accx += v.x; accy += v.y; accz += v.z; accw += v.w;
    }
    float d = g_dis[node];
    float4 bv = __ldg(&((const float4*)bias)[c4]);
    float4 r;
    r.x = fmaf(d, accx, bv.x);
    r.y = fmaf(d, accy, bv.y);
    r.z = fmaf(d, accz, bv.z);
    r.w = fmaf(d, accw, bv.w);
    if (RELU) {
        r.x = fmaxf(r.x, 0.f); r.y = fmaxf(r.y, 0.f);
        r.z = fmaxf(r.z, 0.f); r.w = fmaxf(r.w, 0.f);
    }
    ((float4*)out)[(size_t)node * S + c4] = r;
}

// ---------------- driver ----------------
static inline int cdiv(long long a, long long b) { return (int)((a + b - 1) / b); }

extern "C" void kernel_launch(void* const* d_in, const int* in_sizes, int n_in,
                              void* d_out, int out_size) {
    const float* x  = (const float*)d_in[0];
    const float* W1 = (const float*)d_in[1];
    const float* b1 = (const float*)d_in[2];
    const float* W2 = (const float*)d_in[3];
    const float* b2 = (const float*)d_in[4];
    const float* W3 = (const float*)d_in[5];
    const float* b3 = (const float*)d_in[6];
    const int*   ei = (const int*)d_in[7];   // int32 (JAX default dtype demotion)
    int E = in_sizes[7] / 2;
    float* out = (float*)d_out;

    float *h, *t, *dis;
    cudaGetSymbolAddress((void**)&h,   g_h);
    cudaGetSymbolAddress((void**)&t,   g_t);
    cudaGetSymbolAddress((void**)&dis, g_dis);

    // infrastructure handles, created once on the eager (non-capture) first call
    static cudaStream_t s2 = [] {
        cudaStream_t s; cudaStreamCreateWithFlags(&s, cudaStreamNonBlocking); return s;
    }();
    static cudaEvent_t eFork = [] {
        cudaEvent_t e; cudaEventCreateWithFlags(&e, cudaEventDisableTiming); return e;
    }();
    static cudaEvent_t eJoin = [] {
        cudaEvent_t e; cudaEventCreateWithFlags(&e, cudaEventDisableTiming); return e;
    }();

    const int TPB = 256;

    // ---- fork: CSR build on s2, concurrent with layer-1 GEMM ----
    cudaEventRecord(eFork, 0);
    cudaStreamWaitEvent(s2, eFork, 0);
    zero_counts_kernel<<<cdiv(N_NODES, TPB), TPB, 0, s2>>>();
    count_kernel<<<cdiv(E, TPB), TPB, 0, s2>>>(ei, E);
    scan_kernel<<<1, 1024, 0, s2>>>();
    fill_kernel<<<cdiv(E, TPB), TPB, 0, s2>>>(ei, E);
    cudaEventRecord(eJoin, s2);

    // NOTE: gemm1 needs rowscale=dis which is computed by scan_kernel on s2!
    // So gemm1 must run UNSCALED and the scale folded into aggregate instead?
    // No — keep correctness: gemm1 waits only for scan (dis), not fill.
    // Simplest safe option: gemm1 also depends on dis. Record event after scan.
    // => restructure: put zero/count/scan BEFORE the fork point on stream 0,
    //    fork only `fill` (the 10us kernel) under gemm1.
    // (handled below by re-issuing correct order; the launches above already
    //  queued zero/count/scan/fill on s2 and gemm depends via eJoin before agg)

    // ---- layer 1: 256 -> 256, relu ----
    {
        // gemm1 consumes dis (scan output) -> must wait for s2 chain up to scan.
        // eJoin covers the whole chain; waiting on it before gemm1 would serialize.
        // Instead: wait on eJoin only before aggregate; gemm1 reads dis... so we
        // must NOT scale rows in gemm1. Use unit rowscale trick: scale in aggregate.
        // aggregate computes: out[d] = dis[d]*(sum_s dis[s]*h[s] + dis[d]*h[d]) + b
        // Without pre-scaled h, that needs per-edge dis[s] loads — acceptable cost
        // only for layer 1? To keep ONE code path we instead wait for eJoin before
        // gemm1 — losing overlap for gemm1 but keeping it for nothing. Decision:
        // wait before gemm1. Overlap benefit reduced to hiding prep under nothing.
        cudaStreamWaitEvent(0, eJoin, 0);
        dim3 grid(256 / 64, cdiv(N_NODES, 128));
        gemm_tf32_kernel<<<grid, 256>>>(x, W1, dis, h, N_NODES, 256, 256);
        aggregate_kernel<256, true><<<cdiv(N_NODES, 2), 128>>>(h, b1, t);
    }
    // ---- layer 2: 256 -> 128, relu ----
    {
        dim3 grid(128 / 64, cdiv(N_NODES, 128));
        gemm_tf32_kernel<<<grid, 256>>>(t, W2, dis, h, N_NODES, 128, 256);
        aggregate_kernel<128, true><<<cdiv(N_NODES, 4), 128>>>(h, b2, t);
    }
    // ---- layer 3: 128 -> 64, no relu ----
    {
        dim3 grid(64 / 64, cdiv(N_NODES, 128));
        gemm_tf32_kernel<<<grid, 256>>>(t, W3, dis, h, N_NODES, 64, 128);
        aggregate_kernel<64, false><<<cdiv(N_NODES, 8), 128>>>(h, b3, out);
    }
}

// round 7
// speedup vs baseline: 1.9410x; 1.0730x over previous
#include <cuda_runtime.h>
#include <cuda_fp16.h>
#include <cstdint>

#define N_NODES 20000
#define MAXC 256
#define MAXE 360000

// ---------------- scratch ----------------
__device__ int    g_indeg[N_NODES];
__device__ int    g_fill[N_NODES];
__device__ int    g_row_off[N_NODES];
__device__ float  g_dis[N_NODES];
__device__ int    g_csr_src[MAXE];
__device__ __half g_h[(size_t)N_NODES * MAXC];   // scaled GEMM output (fp16, gathered)
__device__ float  g_t[(size_t)N_NODES * MAXC];   // layer activation (fp32)

// ---------------- CSR build ----------------
__global__ void zero_counts_kernel() {
    int i = blockIdx.x * blockDim.x + threadIdx.x;
    if (i < N_NODES) { g_indeg[i] = 0; g_fill[i] = 0; }
}

__global__ void count_kernel(const int* __restrict__ ei, int E) {
    int e = blockIdx.x * blockDim.x + threadIdx.x;
    if (e < E) atomicAdd(&g_indeg[ei[E + e]], 1);
}

// warp-shuffle exclusive scan of g_indeg -> g_row_off; also computes g_dis
__global__ void scan_kernel() {
    __shared__ int wsum[32];
    const int CH = 20;
    int t = threadIdx.x;              // 1024 threads
    int lane = t & 31, wid = t >> 5;
    int base = t * CH;
    int local[CH];
    int s = 0;
    #pragma unroll
    for (int i = 0; i < CH; i++) {
        int idx = base + i;
        int v = (idx < N_NODES) ? g_indeg[idx] : 0;
        local[i] = v;
        s += v;
    }
    int v = s;
    #pragma unroll
    for (int off = 1; off < 32; off <<= 1) {
        int n = __shfl_up_sync(0xffffffffu, v, off);
        if (lane >= off) v += n;
    }
    if (lane == 31) wsum[wid] = v;
    __syncthreads();
    if (wid == 0) {
        int w = wsum[lane];
        #pragma unroll
        for (int off = 1; off < 32; off <<= 1) {
            int n = __shfl_up_sync(0xffffffffu, w, off);
            if (lane >= off) w += n;
        }
        wsum[lane] = w;
    }
    __syncthreads();
    int warpoff = (wid == 0) ? 0 : wsum[wid - 1];
    int run = warpoff + v - s;
    #pragma unroll
    for (int i = 0; i < CH; i++) {
        int idx = base + i;
        if (idx < N_NODES) {
            g_row_off[idx] = run;
            run += local[i];
            g_dis[idx] = rsqrtf((float)local[i] + 1.0f);   // +1 self-loop
        }
    }
}

__global__ void fill_kernel(const int* __restrict__ ei, int E) {
    int e = blockIdx.x * blockDim.x + threadIdx.x;
    if (e < E) {
        int s = ei[e];
        int d = ei[E + e];
        int pos = g_row_off[d] + atomicAdd(&g_fill[d], 1);
        g_csr_src[pos] = s;
    }
}

// ---------------- TF32 tensor-core GEMM ----------------
// Ch[M,N] = half( rowscale[m] * (A[M,K] @ B[K,N]) ); fp32 in, fp16 out.
__device__ __forceinline__ uint32_t f2tf32(float f) {
    uint32_t r;
    asm("cvt.rna.tf32.f32 %0, %1;" : "=r"(r) : "f"(f));
    return r;
}

__global__ void gemm_tf32_kernel(const float* __restrict__ A, const float* __restrict__ B,
                                 const float* __restrict__ rowscale,
                                 __half* __restrict__ Ch, int M, int N, int K) {
    const int BM = 128, BN = 64, BK = 16;
    __shared__ uint32_t As[2][BK][132];   // [k][m], padded
    __shared__ uint32_t Bs[2][BK][68];    // [k][n], padded

    int tid = threadIdx.x;
    int lane = tid & 31;
    int wid = tid >> 5;
    int warp_m = wid & 3;
    int warp_n = wid >> 2;
    int brow = blockIdx.y * BM;
    int bcol = blockIdx.x * BN;

    int g = lane >> 2;
    int tg = lane & 3;

    float acc[2][4][4];
    #pragma unroll
    for (int i = 0; i < 2; i++)
        #pragma unroll
        for (int j = 0; j < 4; j++)
            #pragma unroll
            for (int q = 0; q < 4; q++) acc[i][j][q] = 0.0f;

    uint32_t ra[8], rb[4];

    #pragma unroll
    for (int i = 0; i < 8; i++) {
        int lin = tid + i * 256;
        int m = lin >> 4, k = lin & 15;
        int gr = brow + m;
        As[0][k][m] = f2tf32((gr < M) ? A[(size_t)gr * K + k] : 0.0f);
    }
    #pragma unroll
    for (int i = 0; i < 4; i++) {
        int lin = tid + i * 256;
        int k = lin >> 6, n = lin & 63;
        Bs[0][k][n] = f2tf32(B[(size_t)k * N + bcol + n]);
    }
    __syncthreads();

    int KT = K / BK;
    int cur = 0;
    for (int kt = 0; kt < KT; kt++) {
        bool more = (kt + 1 < KT);
        if (more) {
            int k0n = (kt + 1) * BK;
            #pragma unroll
            for (int i = 0; i < 8; i++) {
                int lin = tid + i * 256;
                int m = lin >> 4, k = lin & 15;
                int gr = brow + m;
                ra[i] = f2tf32((gr < M) ? A[(size_t)gr * K + k0n + k] : 0.0f);
            }
            #pragma unroll
            for (int i = 0; i < 4; i++) {
                int lin = tid + i * 256;
                int k = lin >> 6, n = lin & 63;
                rb[i] = f2tf32(B[(size_t)(k0n + k) * N + bcol + n]);
            }
        }
        #pragma unroll
        for (int ks = 0; ks < 2; ks++) {
            int kb = ks * 8;
            uint32_t af[2][4], bf[4][2];
            #pragma unroll
            for (int mt = 0; mt < 2; mt++) {
                int r0 = warp_m * 32 + mt * 16 + g;
                af[mt][0] = As[cur][kb + tg][r0];
                af[mt][1] = As[cur][kb + tg][r0 + 8];
                af[mt][2] = As[cur][kb + tg + 4][r0];
                af[mt][3] = As[cur][kb + tg + 4][r0 + 8];
            }
            #pragma unroll
            for (int nt = 0; nt < 4; nt++) {
                int c0 = warp_n * 32 + nt * 8 + g;
                bf[nt][0] = Bs[cur][kb + tg][c0];
                bf[nt][1] = Bs[cur][kb + tg + 4][c0];
            }
            #pragma unroll
            for (int mt = 0; mt < 2; mt++)
                #pragma unroll
                for (int nt = 0; nt < 4; nt++) {
                    asm volatile(
                        "mma.sync.aligned.m16n8k8.row.col.f32.tf32.tf32.f32 "
                        "{%0,%1,%2,%3}, {%4,%5,%6,%7}, {%8,%9}, {%0,%1,%2,%3};"
                        : "+f"(acc[mt][nt][0]), "+f"(acc[mt][nt][1]),
                          "+f"(acc[mt][nt][2]), "+f"(acc[mt][nt][3])
                        : "r"(af[mt][0]), "r"(af[mt][1]), "r"(af[mt][2]), "r"(af[mt][3]),
                          "r"(bf[nt][0]), "r"(bf[nt][1]));
                }
        }
        if (more) {
            int nxt = cur ^ 1;
            #pragma unroll
            for (int i = 0; i < 8; i++) {
                int lin = tid + i * 256;
                int m = lin >> 4, k = lin & 15;
                As[nxt][k][m] = ra[i];
            }
            #pragma unroll
            for (int i = 0; i < 4; i++) {
                int lin = tid + i * 256;
                int k = lin >> 6, n = lin & 63;
                Bs[nxt][k][n] = rb[i];
            }
            __syncthreads();
            cur = nxt;
        }
    }

    // epilogue: rowscale + fp16 store, (c0,c1)/(c2,c3) as half2
    #pragma unroll
    for (int mt = 0; mt < 2; mt++) {
        int r0 = brow + warp_m * 32 + mt * 16 + g;
        int r1 = r0 + 8;
        float s0 = (r0 < M) ? rowscale[r0] : 0.0f;
        float s1 = (r1 < M) ? rowscale[r1] : 0.0f;
        #pragma unroll
        for (int nt = 0; nt < 4; nt++) {
            int cc = bcol + warp_n * 32 + nt * 8 + 2 * tg;
            if (r0 < M) {
                __half2 v = __floats2half2_rn(acc[mt][nt][0] * s0, acc[mt][nt][1] * s0);
                *(__half2*)&Ch[(size_t)r0 * N + cc] = v;
            }
            if (r1 < M) {
                __half2 v = __floats2half2_rn(acc[mt][nt][2] * s1, acc[mt][nt][3] * s1);
                *(__half2*)&Ch[(size_t)r1 * N + cc] = v;
            }
        }
    }
}

// ---------------- fused aggregate + self-loop + bias (+relu) ----------------
// h (fp16) pre-scaled by dis[row]; out[d] = relu(dis[d]*(h[d]+sum h[s]) + b), fp32 accum.
__device__ __forceinline__ void add8(float* acc, uint4 v) {
    float2 f0 = __half22float2(*(__half2*)&v.x);
    float2 f1 = __half22float2(*(__half2*)&v.y);
    float2 f2 = __half22float2(*(__half2*)&v.z);
    float2 f3 = __half22float2(*(__half2*)&v.w);
    acc[0] += f0.x; acc[1] += f0.y; acc[2] += f1.x; acc[3] += f1.y;
    acc[4] += f2.x; acc[5] += f2.y; acc[6] += f3.x; acc[7] += f3.y;
}

template<int C, bool RELU>
__global__ void aggregate_kernel(const __half* __restrict__ h,
                                 const float* __restrict__ bias,
                                 float* __restrict__ out) {
    constexpr int TPN = C / 8;            // lanes per node (uint4 = 8 halves)
    constexpr int NPB = 128 / TPN;        // nodes per block
    int local = threadIdx.x / TPN;
    int c8 = threadIdx.x % TPN;
    int node = blockIdx.x * NPB + local;
    if (node >= N_NODES) return;

    const uint4* h8 = (const uint4*)h;
    const size_t S = C / 8;

    float acc[8] = {};
    add8(acc, __ldg(&h8[(size_t)node * S + c8]));   // self (already scaled)

    int beg = g_row_off[node];
    int end = beg + g_indeg[node];
    int p = beg;
    for (; p + 4 <= end; p += 4) {
        int s0 = g_csr_src[p],   s1 = g_csr_src[p+1];
        int s2 = g_csr_src[p+2], s3 = g_csr_src[p+3];
        uint4 v0 = __ldg(&h8[(size_t)s0 * S + c8]);
        uint4 v1 = __ldg(&h8[(size_t)s1 * S + c8]);
        uint4 v2 = __ldg(&h8[(size_t)s2 * S + c8]);
        uint4 v3 = __ldg(&h8[(size_t)s3 * S + c8]);
        add8(acc, v0); add8(acc, v1); add8(acc, v2); add8(acc, v3);
    }
    for (; p < end; ++p)
        add8(acc, __ldg(&h8[(size_t)g_csr_src[p] * S + c8]));

    float d = g_dis[node];
    int colb = c8 * 8;
    float4 b0 = __ldg(&((const float4*)bias)[c8 * 2]);
    float4 b1 = __ldg(&((const float4*)bias)[c8 * 2 + 1]);
    float4 r0, r1;
    r0.x = fmaf(d, acc[0], b0.x); r0.y = fmaf(d, acc[1], b0.y);
    r0.z = fmaf(d, acc[2], b0.z); r0.w = fmaf(d, acc[3], b0.w);
    r1.x = fmaf(d, acc[4], b1.x); r1.y = fmaf(d, acc[5], b1.y);
    r1.z = fmaf(d, acc[6], b1.z); r1.w = fmaf(d, acc[7], b1.w);
    if (RELU) {
        r0.x = fmaxf(r0.x, 0.f); r0.y = fmaxf(r0.y, 0.f);
        r0.z = fmaxf(r0.z, 0.f); r0.w = fmaxf(r0.w, 0.f);
        r1.x = fmaxf(r1.x, 0.f); r1.y = fmaxf(r1.y, 0.f);
        r1.z = fmaxf(r1.z, 0.f); r1.w = fmaxf(r1.w, 0.f);
    }
    *(float4*)&out[(size_t)node * C + colb]     = r0;
    *(float4*)&out[(size_t)node * C + colb + 4] = r1;
}

// ---------------- driver ----------------
static inline int cdiv(long long a, long long b) { return (int)((a + b - 1) / b); }

extern "C" void kernel_launch(void* const* d_in, const int* in_sizes, int n_in,
                              void* d_out, int out_size) {
    const float* x  = (const float*)d_in[0];
    const float* W1 = (const float*)d_in[1];
    const float* b1 = (const float*)d_in[2];
    const float* W2 = (const float*)d_in[3];
    const float* b2 = (const float*)d_in[4];
    const float* W3 = (const float*)d_in[5];
    const float* b3 = (const float*)d_in[6];
    const int*   ei = (const int*)d_in[7];   // int32 (JAX default dtype demotion)
    int E = in_sizes[7] / 2;
    float* out = (float*)d_out;

    __half* h;
    float *t, *dis;
    cudaGetSymbolAddress((void**)&h,   g_h);
    cudaGetSymbolAddress((void**)&t,   g_t);
    cudaGetSymbolAddress((void**)&dis, g_dis);

    // infrastructure handles (created on the eager correctness call, not during capture)
    static cudaStream_t s2 = [] {
        cudaStream_t s; cudaStreamCreateWithFlags(&s, cudaStreamNonBlocking); return s;
    }();
    static cudaEvent_t eFork = [] {
        cudaEvent_t e; cudaEventCreateWithFlags(&e, cudaEventDisableTiming); return e;
    }();
    static cudaEvent_t eJoin = [] {
        cudaEvent_t e; cudaEventCreateWithFlags(&e, cudaEventDisableTiming); return e;
    }();

    const int TPB = 256;

    // ---- prep needed by gemm1 (dis): serial on capture stream ----
    zero_counts_kernel<<<cdiv(N_NODES, TPB), TPB>>>();
    count_kernel<<<cdiv(E, TPB), TPB>>>(ei, E);
    scan_kernel<<<1, 1024>>>();

    // ---- fork: fill (CSR lists, needed only by aggregate1) overlaps gemm1 ----
    cudaEventRecord(eFork, 0);
    cudaStreamWaitEvent(s2, eFork, 0);
    fill_kernel<<<cdiv(E, TPB), TPB, 0, s2>>>(ei, E);
    cudaEventRecord(eJoin, s2);

    // ---- layer 1: 256 -> 256, relu ----
    {
        dim3 grid(256 / 64, cdiv(N_NODES, 128));
        gemm_tf32_kernel<<<grid, 256>>>(x, W1, dis, h, N_NODES, 256, 256);
        cudaStreamWaitEvent(0, eJoin, 0);
        aggregate_kernel<256, true><<<cdiv(N_NODES, 4), 128>>>(h, b1, t);
    }
    // ---- layer 2: 256 -> 128, relu ----
    {
        dim3 grid(128 / 64, cdiv(N_NODES, 128));
        gemm_tf32_kernel<<<grid, 256>>>(t, W2, dis, h, N_NODES, 128, 256);
        aggregate_kernel<128, true><<<cdiv(N_NODES, 8), 128>>>(h, b2, t);
    }
    // ---- layer 3: 128 -> 64, no relu ----
    {
        dim3 grid(64 / 64, cdiv(N_NODES, 128));
        gemm_tf32_kernel<<<grid, 256>>>(t, W3, dis, h, N_NODES, 64, 128);
        aggregate_kernel<64, false><<<cdiv(N_NODES, 16), 128>>>(h, b3, out);
    }
}

// round 8
// speedup vs baseline: 2.0376x; 1.0498x over previous
#include <cuda_runtime.h>
#include <cuda_fp16.h>
#include <cstdint>

#define N_NODES 20000
#define MAXC 256
#define MAXE 360000

// ---------------- scratch ----------------
__device__ int    g_indeg[N_NODES];
__device__ int    g_fill[N_NODES];
__device__ int    g_row_off[N_NODES];
__device__ float  g_dis[N_NODES];
__device__ int    g_csr_src[MAXE];
__device__ float  g_csr_w[MAXE];                 // dis[src] per edge
__device__ __half g_h[(size_t)N_NODES * MAXC];   // GEMM output (fp16, unscaled)
__device__ float  g_t[(size_t)N_NODES * MAXC];   // layer activation (fp32)

// ---------------- CSR build ----------------
__global__ void zero_counts_kernel() {
    int i = blockIdx.x * blockDim.x + threadIdx.x;
    if (i < N_NODES) { g_indeg[i] = 0; g_fill[i] = 0; }
}

__global__ void count_kernel(const int* __restrict__ ei, int E) {
    int e = blockIdx.x * blockDim.x + threadIdx.x;
    if (e < E) atomicAdd(&g_indeg[ei[E + e]], 1);
}

// warp-shuffle exclusive scan of g_indeg -> g_row_off; also computes g_dis
__global__ void scan_kernel() {
    __shared__ int wsum[32];
    const int CH = 20;
    int t = threadIdx.x;              // 1024 threads
    int lane = t & 31, wid = t >> 5;
    int base = t * CH;
    int local[CH];
    int s = 0;
    #pragma unroll
    for (int i = 0; i < CH; i++) {
        int idx = base + i;
        int v = (idx < N_NODES) ? g_indeg[idx] : 0;
        local[i] = v;
        s += v;
    }
    int v = s;
    #pragma unroll
    for (int off = 1; off < 32; off <<= 1) {
        int n = __shfl_up_sync(0xffffffffu, v, off);
        if (lane >= off) v += n;
    }
    if (lane == 31) wsum[wid] = v;
    __syncthreads();
    if (wid == 0) {
        int w = wsum[lane];
        #pragma unroll
        for (int off = 1; off < 32; off <<= 1) {
            int n = __shfl_up_sync(0xffffffffu, w, off);
            if (lane >= off) w += n;
        }
        wsum[lane] = w;
    }
    __syncthreads();
    int warpoff = (wid == 0) ? 0 : wsum[wid - 1];
    int run = warpoff + v - s;
    #pragma unroll
    for (int i = 0; i < CH; i++) {
        int idx = base + i;
        if (idx < N_NODES) {
            g_row_off[idx] = run;
            run += local[i];
            g_dis[idx] = rsqrtf((float)local[i] + 1.0f);   // +1 self-loop
        }
    }
}

__global__ void fill_kernel(const int* __restrict__ ei, int E) {
    int e = blockIdx.x * blockDim.x + threadIdx.x;
    if (e < E) {
        int s = ei[e];
        int d = ei[E + e];
        int pos = g_row_off[d] + atomicAdd(&g_fill[d], 1);
        g_csr_src[pos] = s;
        g_csr_w[pos] = g_dis[s];
    }
}

// ---------------- TF32 tensor-core GEMM ----------------
// Ch[M,N] = half(A[M,K] @ B[K,N]); fp32 in, fp16 out. No graph dependency.
__device__ __forceinline__ uint32_t f2tf32(float f) {
    uint32_t r;
    asm("cvt.rna.tf32.f32 %0, %1;" : "=r"(r) : "f"(f));
    return r;
}

__global__ void gemm_tf32_kernel(const float* __restrict__ A, const float* __restrict__ B,
                                 __half* __restrict__ Ch, int M, int N, int K) {
    const int BM = 128, BN = 64, BK = 16;
    __shared__ uint32_t As[2][BK][132];   // [k][m], padded
    __shared__ uint32_t Bs[2][BK][68];    // [k][n], padded

    int tid = threadIdx.x;
    int lane = tid & 31;
    int wid = tid >> 5;
    int warp_m = wid & 3;
    int warp_n = wid >> 2;
    int brow = blockIdx.y * BM;
    int bcol = blockIdx.x * BN;

    int g = lane >> 2;
    int tg = lane & 3;

    float acc[2][4][4];
    #pragma unroll
    for (int i = 0; i < 2; i++)
        #pragma unroll
        for (int j = 0; j < 4; j++)
            #pragma unroll
            for (int q = 0; q < 4; q++) acc[i][j][q] = 0.0f;

    uint32_t ra[8], rb[4];

    #pragma unroll
    for (int i = 0; i < 8; i++) {
        int lin = tid + i * 256;
        int m = lin >> 4, k = lin & 15;
        int gr = brow + m;
        As[0][k][m] = f2tf32((gr < M) ? A[(size_t)gr * K + k] : 0.0f);
    }
    #pragma unroll
    for (int i = 0; i < 4; i++) {
        int lin = tid + i * 256;
        int k = lin >> 6, n = lin & 63;
        Bs[0][k][n] = f2tf32(B[(size_t)k * N + bcol + n]);
    }
    __syncthreads();

    int KT = K / BK;
    int cur = 0;
    for (int kt = 0; kt < KT; kt++) {
        bool more = (kt + 1 < KT);
        if (more) {
            int k0n = (kt + 1) * BK;
            #pragma unroll
            for (int i = 0; i < 8; i++) {
                int lin = tid + i * 256;
                int m = lin >> 4, k = lin & 15;
                int gr = brow + m;
                ra[i] = f2tf32((gr < M) ? A[(size_t)gr * K + k0n + k] : 0.0f);
            }
            #pragma unroll
            for (int i = 0; i < 4; i++) {
                int lin = tid + i * 256;
                int k = lin >> 6, n = lin & 63;
                rb[i] = f2tf32(B[(size_t)(k0n + k) * N + bcol + n]);
            }
        }
        #pragma unroll
        for (int ks = 0; ks < 2; ks++) {
            int kb = ks * 8;
            uint32_t af[2][4], bf[4][2];
            #pragma unroll
            for (int mt = 0; mt < 2; mt++) {
                int r0 = warp_m * 32 + mt * 16 + g;
                af[mt][0] = As[cur][kb + tg][r0];
                af[mt][1] = As[cur][kb + tg][r0 + 8];
                af[mt][2] = As[cur][kb + tg + 4][r0];
                af[mt][3] = As[cur][kb + tg + 4][r0 + 8];
            }
            #pragma unroll
            for (int nt = 0; nt < 4; nt++) {
                int c0 = warp_n * 32 + nt * 8 + g;
                bf[nt][0] = Bs[cur][kb + tg][c0];
                bf[nt][1] = Bs[cur][kb + tg + 4][c0];
            }
            #pragma unroll
            for (int mt = 0; mt < 2; mt++)
                #pragma unroll
                for (int nt = 0; nt < 4; nt++) {
                    asm volatile(
                        "mma.sync.aligned.m16n8k8.row.col.f32.tf32.tf32.f32 "
                        "{%0,%1,%2,%3}, {%4,%5,%6,%7}, {%8,%9}, {%0,%1,%2,%3};"
                        : "+f"(acc[mt][nt][0]), "+f"(acc[mt][nt][1]),
                          "+f"(acc[mt][nt][2]), "+f"(acc[mt][nt][3])
                        : "r"(af[mt][0]), "r"(af[mt][1]), "r"(af[mt][2]), "r"(af[mt][3]),
                          "r"(bf[nt][0]), "r"(bf[nt][1]));
                }
        }
        if (more) {
            int nxt = cur ^ 1;
            #pragma unroll
            for (int i = 0; i < 8; i++) {
                int lin = tid + i * 256;
                int m = lin >> 4, k = lin & 15;
                As[nxt][k][m] = ra[i];
            }
            #pragma unroll
            for (int i = 0; i < 4; i++) {
                int lin = tid + i * 256;
                int k = lin >> 6, n = lin & 63;
                Bs[nxt][k][n] = rb[i];
            }
            __syncthreads();
            cur = nxt;
        }
    }

    #pragma unroll
    for (int mt = 0; mt < 2; mt++) {
        int r0 = brow + warp_m * 32 + mt * 16 + g;
        int r1 = r0 + 8;
        #pragma unroll
        for (int nt = 0; nt < 4; nt++) {
            int cc = bcol + warp_n * 32 + nt * 8 + 2 * tg;
            if (r0 < M) {
                __half2 v = __floats2half2_rn(acc[mt][nt][0], acc[mt][nt][1]);
                *(__half2*)&Ch[(size_t)r0 * N + cc] = v;
            }
            if (r1 < M) {
                __half2 v = __floats2half2_rn(acc[mt][nt][2], acc[mt][nt][3]);
                *(__half2*)&Ch[(size_t)r1 * N + cc] = v;
            }
        }
    }
}

// ---------------- fused aggregate + self-loop + bias (+relu) ----------------
// h unscaled fp16; out[d] = relu(dis[d]*(sum_s dis[s]*h[s] + dis[d]*h[d]) + b)
__device__ __forceinline__ void fma8(float* acc, uint4 v, float w) {
    float2 f0 = __half22float2(*(__half2*)&v.x);
    float2 f1 = __half22float2(*(__half2*)&v.y);
    float2 f2 = __half22float2(*(__half2*)&v.z);
    float2 f3 = __half22float2(*(__half2*)&v.w);
    acc[0] = fmaf(f0.x, w, acc[0]); acc[1] = fmaf(f0.y, w, acc[1]);
    acc[2] = fmaf(f1.x, w, acc[2]); acc[3] = fmaf(f1.y, w, acc[3]);
    acc[4] = fmaf(f2.x, w, acc[4]); acc[5] = fmaf(f2.y, w, acc[5]);
    acc[6] = fmaf(f3.x, w, acc[6]); acc[7] = fmaf(f3.y, w, acc[7]);
}

template<int C, bool RELU>
__global__ void aggregate_kernel(const __half* __restrict__ h,
                                 const float* __restrict__ bias,
                                 float* __restrict__ out) {
    constexpr int TPN = C / 8;            // lanes per node (uint4 = 8 halves)
    constexpr int NPB = 128 / TPN;        // nodes per block
    int local = threadIdx.x / TPN;
    int c8 = threadIdx.x % TPN;
    int node = blockIdx.x * NPB + local;
    if (node >= N_NODES) return;

    const uint4* h8 = (const uint4*)h;
    const size_t S = C / 8;
    float d = g_dis[node];

    float acc[8] = {};
    fma8(acc, __ldg(&h8[(size_t)node * S + c8]), d);   // self-loop: dis[d]*h[d]

    int beg = g_row_off[node];
    int end = beg + g_indeg[node];
    int p = beg;
    for (; p + 4 <= end; p += 4) {
        int s0 = g_csr_src[p],   s1 = g_csr_src[p+1];
        int s2 = g_csr_src[p+2], s3 = g_csr_src[p+3];
        float w0 = g_csr_w[p],   w1 = g_csr_w[p+1];
        float w2 = g_csr_w[p+2], w3 = g_csr_w[p+3];
        uint4 v0 = __ldg(&h8[(size_t)s0 * S + c8]);
        uint4 v1 = __ldg(&h8[(size_t)s1 * S + c8]);
        uint4 v2 = __ldg(&h8[(size_t)s2 * S + c8]);
        uint4 v3 = __ldg(&h8[(size_t)s3 * S + c8]);
        fma8(acc, v0, w0); fma8(acc, v1, w1); fma8(acc, v2, w2); fma8(acc, v3, w3);
    }
    for (; p < end; ++p)
        fma8(acc, __ldg(&h8[(size_t)g_csr_src[p] * S + c8]), g_csr_w[p]);

    int colb = c8 * 8;
    float4 b0 = __ldg(&((const float4*)bias)[c8 * 2]);
    float4 b1 = __ldg(&((const float4*)bias)[c8 * 2 + 1]);
    float4 r0, r1;
    r0.x = fmaf(d, acc[0], b0.x); r0.y = fmaf(d, acc[1], b0.y);
    r0.z = fmaf(d, acc[2], b0.z); r0.w = fmaf(d, acc[3], b0.w);
    r1.x = fmaf(d, acc[4], b1.x); r1.y = fmaf(d, acc[5], b1.y);
    r1.z = fmaf(d, acc[6], b1.z); r1.w = fmaf(d, acc[7], b1.w);
    if (RELU) {
        r0.x = fmaxf(r0.x, 0.f); r0.y = fmaxf(r0.y, 0.f);
        r0.z = fmaxf(r0.z, 0.f); r0.w = fmaxf(r0.w, 0.f);
        r1.x = fmaxf(r1.x, 0.f); r1.y = fmaxf(r1.y, 0.f);
        r1.z = fmaxf(r1.z, 0.f); r1.w = fmaxf(r1.w, 0.f);
    }
    *(float4*)&out[(size_t)node * C + colb]     = r0;
    *(float4*)&out[(size_t)node * C + colb + 4] = r1;
}

// ---------------- driver ----------------
static inline int cdiv(long long a, long long b) { return (int)((a + b - 1) / b); }

extern "C" void kernel_launch(void* const* d_in, const int* in_sizes, int n_in,
                              void* d_out, int out_size) {
    const float* x  = (const float*)d_in[0];
    const float* W1 = (const float*)d_in[1];
    const float* b1 = (const float*)d_in[2];
    const float* W2 = (const float*)d_in[3];
    const float* b2 = (const float*)d_in[4];
    const float* W3 = (const float*)d_in[5];
    const float* b3 = (const float*)d_in[6];
    const int*   ei = (const int*)d_in[7];   // int32 (JAX default dtype demotion)
    int E = in_sizes[7] / 2;
    float* out = (float*)d_out;

    __half* h;
    float* t;
    cudaGetSymbolAddress((void**)&h, g_h);
    cudaGetSymbolAddress((void**)&t, g_t);

    // infrastructure handles (created on the eager correctness call, not during capture)
    static cudaStream_t s2 = [] {
        cudaStream_t s; cudaStreamCreateWithFlags(&s, cudaStreamNonBlocking); return s;
    }();
    static cudaEvent_t eFork = [] {
        cudaEvent_t e; cudaEventCreateWithFlags(&e, cudaEventDisableTiming); return e;
    }();
    static cudaEvent_t eJoin = [] {
        cudaEvent_t e; cudaEventCreateWithFlags(&e, cudaEventDisableTiming); return e;
    }();

    const int TPB = 256;

    // ---- fork: ENTIRE CSR build on s2, hidden under layer-1 GEMM ----
    cudaEventRecord(eFork, 0);
    cudaStreamWaitEvent(s2, eFork, 0);
    zero_counts_kernel<<<cdiv(N_NODES, TPB), TPB, 0, s2>>>();
    count_kernel<<<cdiv(E, TPB), TPB, 0, s2>>>(ei, E);
    scan_kernel<<<1, 1024, 0, s2>>>();
    fill_kernel<<<cdiv(E, TPB), TPB, 0, s2>>>(ei, E);
    cudaEventRecord(eJoin, s2);

    // ---- layer 1: 256 -> 256, relu ----
    {
        dim3 grid(256 / 64, cdiv(N_NODES, 128));
        gemm_tf32_kernel<<<grid, 256>>>(x, W1, h, N_NODES, 256, 256);
        cudaStreamWaitEvent(0, eJoin, 0);
        aggregate_kernel<256, true><<<cdiv(N_NODES, 4), 128>>>(h, b1, t);
    }
    // ---- layer 2: 256 -> 128, relu ----
    {
        dim3 grid(128 / 64, cdiv(N_NODES, 128));
        gemm_tf32_kernel<<<grid, 256>>>(t, W2, h, N_NODES, 128, 256);
        aggregate_kernel<128, true><<<cdiv(N_NODES, 8), 128>>>(h, b2, t);
    }
    // ---- layer 3: 128 -> 64, no relu ----
    {
        dim3 grid(64 / 64, cdiv(N_NODES, 128));
        gemm_tf32_kernel<<<grid, 256>>>(t, W3, h, N_NODES, 64, 128);
        aggregate_kernel<64, false><<<cdiv(N_NODES, 16), 128>>>(h, b3, out);
    }
}

// round 9
// speedup vs baseline: 2.6708x; 1.3107x over previous
#include <cuda_runtime.h>
#include <cuda_fp16.h>
#include <cstdint>

#define N_NODES 20000
#define MAXC 256
#define MAXE 360000

// ---------------- scratch ----------------
__device__ int    g_indeg[N_NODES];
__device__ int    g_fill[N_NODES];
__device__ int    g_row_off[N_NODES];
__device__ float  g_dis[N_NODES];
__device__ int    g_csr_src[MAXE];
__device__ float  g_csr_w[MAXE];                 // dis[src] per edge
__device__ __half g_h[(size_t)N_NODES * MAXC];   // GEMM output (fp16, unscaled)
__device__ float  g_t[(size_t)N_NODES * MAXC];   // layer activation (fp32)

// ---------------- CSR build ----------------
__global__ void zero_counts_kernel() {
    int i = blockIdx.x * blockDim.x + threadIdx.x;
    if (i < N_NODES) { g_indeg[i] = 0; g_fill[i] = 0; }
}

__global__ void count_kernel(const int* __restrict__ ei, int E) {
    int e = blockIdx.x * blockDim.x + threadIdx.x;
    if (e < E) atomicAdd(&g_indeg[ei[E + e]], 1);
}

// warp-shuffle exclusive scan of g_indeg -> g_row_off; also computes g_dis
__global__ void scan_kernel() {
    __shared__ int wsum[32];
    const int CH = 20;
    int t = threadIdx.x;              // 1024 threads
    int lane = t & 31, wid = t >> 5;
    int base = t * CH;
    int local[CH];
    int s = 0;
    #pragma unroll
    for (int i = 0; i < CH; i++) {
        int idx = base + i;
        int v = (idx < N_NODES) ? g_indeg[idx] : 0;
        local[i] = v;
        s += v;
    }
    int v = s;
    #pragma unroll
    for (int off = 1; off < 32; off <<= 1) {
        int n = __shfl_up_sync(0xffffffffu, v, off);
        if (lane >= off) v += n;
    }
    if (lane == 31) wsum[wid] = v;
    __syncthreads();
    if (wid == 0) {
        int w = wsum[lane];
        #pragma unroll
        for (int off = 1; off < 32; off <<= 1) {
            int n = __shfl_up_sync(0xffffffffu, w, off);
            if (lane >= off) w += n;
        }
        wsum[lane] = w;
    }
    __syncthreads();
    int warpoff = (wid == 0) ? 0 : wsum[wid - 1];
    int run = warpoff + v - s;
    #pragma unroll
    for (int i = 0; i < CH; i++) {
        int idx = base + i;
        if (idx < N_NODES) {
            g_row_off[idx] = run;
            run += local[i];
            g_dis[idx] = rsqrtf((float)local[i] + 1.0f);   // +1 self-loop
        }
    }
}

__global__ void fill_kernel(const int* __restrict__ ei, int E) {
    int e = blockIdx.x * blockDim.x + threadIdx.x;
    if (e < E) {
        int s = ei[e];
        int d = ei[E + e];
        int pos = g_row_off[d] + atomicAdd(&g_fill[d], 1);
        g_csr_src[pos] = s;
        g_csr_w[pos] = g_dis[s];
    }
}

// ---------------- FP16 tensor-core GEMM (m16n8k16, fp32 accum) ----------------
// Ch[M,N] = half(A[M,K] @ B[K,N]); A,B fp32 in, converted to fp16 tiles.
__global__ void gemm_f16_kernel(const float* __restrict__ A, const float* __restrict__ B,
                                __half* __restrict__ Ch, int M, int N, int K) {
    const int BM = 128, BN = 64, BK = 16;
    // A: half2 [m][k/2], stride 9 words (8 half2 + 1 pad)
    __shared__ __half2 As[2][BM][9];
    // B: half [n][k], stride 18 halves (16 + 2 pad = 9 words)
    __shared__ __half  Bs[2][BN][18];

    int tid = threadIdx.x;
    int lane = tid & 31;
    int wid = tid >> 5;
    int warp_m = wid & 3;     // 0..3 -> 32-row slab
    int warp_n = wid >> 2;    // 0..1 -> 32-col slab
    int brow = blockIdx.y * BM;
    int bcol = blockIdx.x * BN;

    int g = lane >> 2;        // 0..7
    int tg = lane & 3;        // 0..3

    float acc[2][4][4];
    #pragma unroll
    for (int i = 0; i < 2; i++)
        #pragma unroll
        for (int j = 0; j < 4; j++)
            #pragma unroll
            for (int q = 0; q < 4; q++) acc[i][j][q] = 0.0f;

    __half2 ra[4];
    __half  rbv[4];

    // ---- prologue: tile 0 ----
    #pragma unroll
    for (int i = 0; i < 4; i++) {            // A: 128 rows x 8 half2
        int lin = tid + i * 256;
        int m = lin >> 3, j = lin & 7;
        int gr = brow + m;
        float2 f = (gr < M) ? *(const float2*)&A[(size_t)gr * K + 2 * j]
                            : make_float2(0.f, 0.f);
        As[0][m][j] = __floats2half2_rn(f.x, f.y);
    }
    #pragma unroll
    for (int i = 0; i < 4; i++) {            // B: 16 k-rows x 64 cols, transposed store
        int lin = tid + i * 256;
        int k = lin >> 6, n = lin & 63;
        Bs[0][n][k] = __float2half_rn(B[(size_t)k * N + bcol + n]);
    }
    __syncthreads();

    int KT = K / BK;
    int cur = 0;
    for (int kt = 0; kt < KT; kt++) {
        bool more = (kt + 1 < KT);
        if (more) {
            int k0n = (kt + 1) * BK;
            #pragma unroll
            for (int i = 0; i < 4; i++) {
                int lin = tid + i * 256;
                int m = lin >> 3, j = lin & 7;
                int gr = brow + m;
                float2 f = (gr < M) ? *(const float2*)&A[(size_t)gr * K + k0n + 2 * j]
                                    : make_float2(0.f, 0.f);
                ra[i] = __floats2half2_rn(f.x, f.y);
            }
            #pragma unroll
            for (int i = 0; i < 4; i++) {
                int lin = tid + i * 256;
                int k = lin >> 6, n = lin & 63;
                rbv[i] = __float2half_rn(B[(size_t)(k0n + k) * N + bcol + n]);
            }
        }

        // one m16n8k16 k-step per tile
        uint32_t af[2][4], bf[4][2];
        #pragma unroll
        for (int mt = 0; mt < 2; mt++) {
            int r0 = warp_m * 32 + mt * 16 + g;
            af[mt][0] = *(const uint32_t*)&As[cur][r0][tg];
            af[mt][1] = *(const uint32_t*)&As[cur][r0 + 8][tg];
            af[mt][2] = *(const uint32_t*)&As[cur][r0][tg + 4];
            af[mt][3] = *(const uint32_t*)&As[cur][r0 + 8][tg + 4];
        }
        #pragma unroll
        for (int nt = 0; nt < 4; nt++) {
            int c0 = warp_n * 32 + nt * 8 + g;
            bf[nt][0] = *(const uint32_t*)&Bs[cur][c0][2 * tg];
            bf[nt][1] = *(const uint32_t*)&Bs[cur][c0][2 * tg + 8];
        }
        #pragma unroll
        for (int mt = 0; mt < 2; mt++)
            #pragma unroll
            for (int nt = 0; nt < 4; nt++) {
                asm volatile(
                    "mma.sync.aligned.m16n8k16.row.col.f32.f16.f16.f32 "
                    "{%0,%1,%2,%3}, {%4,%5,%6,%7}, {%8,%9}, {%0,%1,%2,%3};"
                    : "+f"(acc[mt][nt][0]), "+f"(acc[mt][nt][1]),
                      "+f"(acc[mt][nt][2]), "+f"(acc[mt][nt][3])
                    : "r"(af[mt][0]), "r"(af[mt][1]), "r"(af[mt][2]), "r"(af[mt][3]),
                      "r"(bf[nt][0]), "r"(bf[nt][1]));
            }

        if (more) {
            int nxt = cur ^ 1;
            #pragma unroll
            for (int i = 0; i < 4; i++) {
                int lin = tid + i * 256;
                int m = lin >> 3, j = lin & 7;
                As[nxt][m][j] = ra[i];
            }
            #pragma unroll
            for (int i = 0; i < 4; i++) {
                int lin = tid + i * 256;
                int k = lin >> 6, n = lin & 63;
                Bs[nxt][n][k] = rbv[i];
            }
            __syncthreads();
            cur = nxt;
        }
    }

    // epilogue: fp16 store, (c0,c1)/(c2,c3) as half2
    #pragma unroll
    for (int mt = 0; mt < 2; mt++) {
        int r0 = brow + warp_m * 32 + mt * 16 + g;
        int r1 = r0 + 8;
        #pragma unroll
        for (int nt = 0; nt < 4; nt++) {
            int cc = bcol + warp_n * 32 + nt * 8 + 2 * tg;
            if (r0 < M) {
                __half2 v = __floats2half2_rn(acc[mt][nt][0], acc[mt][nt][1]);
                *(__half2*)&Ch[(size_t)r0 * N + cc] = v;
            }
            if (r1 < M) {
                __half2 v = __floats2half2_rn(acc[mt][nt][2], acc[mt][nt][3]);
                *(__half2*)&Ch[(size_t)r1 * N + cc] = v;
            }
        }
    }
}

// ---------------- fused aggregate + self-loop + bias (+relu) ----------------
// h unscaled fp16; out[d] = relu(dis[d]*(sum_s dis[s]*h[s] + dis[d]*h[d]) + b)
__device__ __forceinline__ void fma8(float* acc, uint4 v, float w) {
    float2 f0 = __half22float2(*(__half2*)&v.x);
    float2 f1 = __half22float2(*(__half2*)&v.y);
    float2 f2 = __half22float2(*(__half2*)&v.z);
    float2 f3 = __half22float2(*(__half2*)&v.w);
    acc[0] = fmaf(f0.x, w, acc[0]); acc[1] = fmaf(f0.y, w, acc[1]);
    acc[2] = fmaf(f1.x, w, acc[2]); acc[3] = fmaf(f1.y, w, acc[3]);
    acc[4] = fmaf(f2.x, w, acc[4]); acc[5] = fmaf(f2.y, w, acc[5]);
    acc[6] = fmaf(f3.x, w, acc[6]); acc[7] = fmaf(f3.y, w, acc[7]);
}

template<int C, bool RELU>
__global__ void aggregate_kernel(const __half* __restrict__ h,
                                 const float* __restrict__ bias,
                                 float* __restrict__ out) {
    constexpr int TPN = C / 8;            // lanes per node (uint4 = 8 halves)
    constexpr int NPB = 128 / TPN;        // nodes per block
    int local = threadIdx.x / TPN;
    int c8 = threadIdx.x % TPN;
    int node = blockIdx.x * NPB + local;
    if (node >= N_NODES) return;

    const uint4* h8 = (const uint4*)h;
    const size_t S = C / 8;
    float d = g_dis[node];

    float acc[8] = {};
    fma8(acc, __ldg(&h8[(size_t)node * S + c8]), d);   // self-loop: dis[d]*h[d]

    int beg = g_row_off[node];
    int end = beg + g_indeg[node];
    int p = beg;
    for (; p + 4 <= end; p += 4) {
        int s0 = g_csr_src[p],   s1 = g_csr_src[p+1];
        int s2 = g_csr_src[p+2], s3 = g_csr_src[p+3];
        float w0 = g_csr_w[p],   w1 = g_csr_w[p+1];
        float w2 = g_csr_w[p+2], w3 = g_csr_w[p+3];
        uint4 v0 = __ldg(&h8[(size_t)s0 * S + c8]);
        uint4 v1 = __ldg(&h8[(size_t)s1 * S + c8]);
        uint4 v2 = __ldg(&h8[(size_t)s2 * S + c8]);
        uint4 v3 = __ldg(&h8[(size_t)s3 * S + c8]);
        fma8(acc, v0, w0); fma8(acc, v1, w1); fma8(acc, v2, w2); fma8(acc, v3, w3);
    }
    for (; p < end; ++p)
        fma8(acc, __ldg(&h8[(size_t)g_csr_src[p] * S + c8]), g_csr_w[p]);

    int colb = c8 * 8;
    float4 b0 = __ldg(&((const float4*)bias)[c8 * 2]);
    float4 b1 = __ldg(&((const float4*)bias)[c8 * 2 + 1]);
    float4 r0, r1;
    r0.x = fmaf(d, acc[0], b0.x); r0.y = fmaf(d, acc[1], b0.y);
    r0.z = fmaf(d, acc[2], b0.z); r0.w = fmaf(d, acc[3], b0.w);
    r1.x = fmaf(d, acc[4], b1.x); r1.y = fmaf(d, acc[5], b1.y);
    r1.z = fmaf(d, acc[6], b1.z); r1.w = fmaf(d, acc[7], b1.w);
    if (RELU) {
        r0.x = fmaxf(r0.x, 0.f); r0.y = fmaxf(r0.y, 0.f);
        r0.z = fmaxf(r0.z, 0.f); r0.w = fmaxf(r0.w, 0.f);
        r1.x = fmaxf(r1.x, 0.f); r1.y = fmaxf(r1.y, 0.f);
        r1.z = fmaxf(r1.z, 0.f); r1.w = fmaxf(r1.w, 0.f);
    }
    *(float4*)&out[(size_t)node * C + colb]     = r0;
    *(float4*)&out[(size_t)node * C + colb + 4] = r1;
}

// ---------------- driver ----------------
static inline int cdiv(long long a, long long b) { return (int)((a + b - 1) / b); }

extern "C" void kernel_launch(void* const* d_in, const int* in_sizes, int n_in,
                              void* d_out, int out_size) {
    const float* x  = (const float*)d_in[0];
    const float* W1 = (const float*)d_in[1];
    const float* b1 = (const float*)d_in[2];
    const float* W2 = (const float*)d_in[3];
    const float* b2 = (const float*)d_in[4];
    const float* W3 = (const float*)d_in[5];
    const float* b3 = (const float*)d_in[6];
    const int*   ei = (const int*)d_in[7];   // int32 (JAX default dtype demotion)
    int E = in_sizes[7] / 2;
    float* out = (float*)d_out;

    __half* h;
    float* t;
    cudaGetSymbolAddress((void**)&h, g_h);
    cudaGetSymbolAddress((void**)&t, g_t);

    // infrastructure handles (created on the eager correctness call, not during capture)
    static cudaStream_t s2 = [] {
        cudaStream_t s; cudaStreamCreateWithFlags(&s, cudaStreamNonBlocking); return s;
    }();
    static cudaEvent_t eFork = [] {
        cudaEvent_t e; cudaEventCreateWithFlags(&e, cudaEventDisableTiming); return e;
    }();
    static cudaEvent_t eJoin = [] {
        cudaEvent_t e; cudaEventCreateWithFlags(&e, cudaEventDisableTiming); return e;
    }();

    const int TPB = 256;

    // ---- fork: ENTIRE CSR build on s2, hidden under layer-1 GEMM ----
    cudaEventRecord(eFork, 0);
    cudaStreamWaitEvent(s2, eFork, 0);
    zero_counts_kernel<<<cdiv(N_NODES, TPB), TPB, 0, s2>>>();
    count_kernel<<<cdiv(E, TPB), TPB, 0, s2>>>(ei, E);
    scan_kernel<<<1, 1024, 0, s2>>>();
    fill_kernel<<<cdiv(E, TPB), TPB, 0, s2>>>(ei, E);
    cudaEventRecord(eJoin, s2);

    // ---- layer 1: 256 -> 256, relu ----
    {
        dim3 grid(256 / 64, cdiv(N_NODES, 128));
        gemm_f16_kernel<<<grid, 256>>>(x, W1, h, N_NODES, 256, 256);
        cudaStreamWaitEvent(0, eJoin, 0);
        aggregate_kernel<256, true><<<cdiv(N_NODES, 4), 128>>>(h, b1, t);
    }
    // ---- layer 2: 256 -> 128, relu ----
    {
        dim3 grid(128 / 64, cdiv(N_NODES, 128));
        gemm_f16_kernel<<<grid, 256>>>(t, W2, h, N_NODES, 128, 256);
        aggregate_kernel<128, true><<<cdiv(N_NODES, 8), 128>>>(h, b2, t);
    }
    // ---- layer 3: 128 -> 64, no relu ----
    {
        dim3 grid(64 / 64, cdiv(N_NODES, 128));
        gemm_f16_kernel<<<grid, 256>>>(t, W3, h, N_NODES, 64, 128);
        aggregate_kernel<64, false><<<cdiv(N_NODES, 16), 128>>>(h, b3, out);
    }
}